// round 9
// baseline (speedup 1.0000x reference)
#include <cuda_runtime.h>
#include <cuda_fp16.h>
#include <math.h>

#define NND 100000
#define NE  3200000
#define LTOK 64
#define HID 16
#define EF  5

struct __align__(32) V8 { uint4 a, b; };
struct __align__(32) F8 { float4 a, b; };

// ---- scratch (device globals; no allocation allowed) ----
__device__ float g_dinv[NND];
__device__ int   g_deg[NND];
__device__ F8    g_Ms1[NND * 2];   // row n = [2n],[2n+1]; UNSCALED X@w1+b1
__device__ F8    g_Ms2[NND * 2];   // pre-scaled by dinv
__device__ F8    g_agg1[NND * 2];
__device__ F8    g_agg2[NND * 2];
__device__ V8    g_Ah[NND];        // A row = 16 half = 32B
__device__ V8    g_Bh[NND];
__device__ __align__(16) int2 g_ve[NE + 2];
__device__ __align__(16) unsigned char g_b8[NND];
__device__ int   g_vcnt;
__device__ unsigned          g_arrive = 0;
__device__ volatile unsigned g_gen   = 0;

__device__ __forceinline__ void red_add_v4(float* p, float4 v) {
    asm volatile("red.global.add.v4.f32 [%0], {%1, %2, %3, %4};"
                 :: "l"(p), "f"(v.x), "f"(v.y), "f"(v.z), "f"(v.w) : "memory");
}
__device__ __forceinline__ V8 ldg256u(const V8* p) {
    V8 r;
    asm volatile("ld.global.nc.v8.b32 {%0,%1,%2,%3,%4,%5,%6,%7}, [%8];"
        : "=r"(r.a.x), "=r"(r.a.y), "=r"(r.a.z), "=r"(r.a.w),
          "=r"(r.b.x), "=r"(r.b.y), "=r"(r.b.z), "=r"(r.b.w)
        : "l"(p));
    return r;
}
__device__ __forceinline__ F8 ldg256f(const F8* p) {
    F8 r;
    asm volatile("ld.global.nc.v8.f32 {%0,%1,%2,%3,%4,%5,%6,%7}, [%8];"
        : "=f"(r.a.x), "=f"(r.a.y), "=f"(r.a.z), "=f"(r.a.w),
          "=f"(r.b.x), "=f"(r.b.y), "=f"(r.b.z), "=f"(r.b.w)
        : "l"(p));
    return r;
}
__device__ __forceinline__ float4 ldcg128(const float4* p) {
    float4 r;
    asm volatile("ld.global.cg.v4.f32 {%0,%1,%2,%3}, [%4];"
        : "=f"(r.x), "=f"(r.y), "=f"(r.z), "=f"(r.w) : "l"(p));
    return r;
}
__device__ __forceinline__ void stg256f(F8* p, const float* v) {
    asm volatile("st.global.v8.f32 [%0], {%1,%2,%3,%4,%5,%6,%7,%8};"
        :: "l"(p), "f"(v[0]), "f"(v[1]), "f"(v[2]), "f"(v[3]),
           "f"(v[4]), "f"(v[5]), "f"(v[6]), "f"(v[7]) : "memory");
}
__device__ __forceinline__ void stg256u(V8* p, const unsigned* v) {
    asm volatile("st.global.v8.b32 [%0], {%1,%2,%3,%4,%5,%6,%7,%8};"
        :: "l"(p), "r"(v[0]), "r"(v[1]), "r"(v[2]), "r"(v[3]),
           "r"(v[4]), "r"(v[5]), "r"(v[6]), "r"(v[7]) : "memory");
}

// ---------------- K0: zero degree + counter + pack batch->u8 ----------------
__global__ void k_prep(const int* __restrict__ batch) {
    int i = blockIdx.x * blockDim.x + threadIdx.x;
    if (i < NND) {
        g_deg[i] = 0;
        g_b8[i] = (unsigned char)batch[i];
    }
    if (i == 0) g_vcnt = 0;
}

// ---------------- K1: heterogeneous deg_compact (even blocks) || encode (odd blocks) ----------------
#define H_BLOCKS 296
#define H_THREADS 512
#define H_HALF_TH (148 * H_THREADS)   // 75776 threads per role

__global__ void __launch_bounds__(H_THREADS) k_deg_encode(
    const int* __restrict__ ei,
    const int* __restrict__ seq, const float* __restrict__ xcov,
    const float* __restrict__ embed, const float* __restrict__ w1,
    const float* __restrict__ b1)
{
    extern __shared__ char dsm[];
    const int t = threadIdx.x;
    const int role = blockIdx.x & 1;
    const int rb = blockIdx.x >> 1;       // 0..147 within role
    const int base_t = rb * H_THREADS + t;

    if (role == 0) {
        // ---- degree + valid-edge compaction via smem batch table ----
        unsigned char* s_b8 = reinterpret_cast<unsigned char*>(dsm);
        {
            const int4* src = reinterpret_cast<const int4*>(g_b8);
            int4* dst = reinterpret_cast<int4*>(s_b8);
            for (int j = t; j < NND / 16; j += H_THREADS) dst[j] = src[j];
        }
        __syncthreads();

        const int NCH = NE / 8;                         // 400000
        const int ITERS = (NCH + H_HALF_TH - 1) / H_HALF_TH;  // 6
        int lane = t & 31;
        for (int it = 0; it < ITERS; it++) {
            int i = base_t + it * H_HALF_TH;
            bool active = (i < NCH);
            int sv[8], dv[8];
            bool v[8];
            int cnt = 0;
            if (active) {
                int base_e = i * 8;
                V8 sa = ldg256u(reinterpret_cast<const V8*>(ei + base_e));
                V8 da = ldg256u(reinterpret_cast<const V8*>(ei + NE + base_e));
                sv[0]=sa.a.x; sv[1]=sa.a.y; sv[2]=sa.a.z; sv[3]=sa.a.w;
                sv[4]=sa.b.x; sv[5]=sa.b.y; sv[6]=sa.b.z; sv[7]=sa.b.w;
                dv[0]=da.a.x; dv[1]=da.a.y; dv[2]=da.a.z; dv[3]=da.a.w;
                dv[4]=da.b.x; dv[5]=da.b.y; dv[6]=da.b.z; dv[7]=da.b.w;
#pragma unroll
                for (int j = 0; j < 8; j++) {
                    v[j] = (s_b8[sv[j]] == s_b8[dv[j]]);
                    if (v[j]) { atomicAdd(&g_deg[sv[j]], 1); cnt++; }
                }
            } else {
#pragma unroll
                for (int j = 0; j < 8; j++) v[j] = false;
            }
            int incl = cnt;
#pragma unroll
            for (int off = 1; off < 32; off <<= 1) {
                int nv = __shfl_up_sync(0xffffffffu, incl, off);
                if (lane >= off) incl += nv;
            }
            int total = __shfl_sync(0xffffffffu, incl, 31);
            int basew = 0;
            if (lane == 31 && total > 0) basew = atomicAdd(&g_vcnt, total);
            basew = __shfl_sync(0xffffffffu, basew, 31);
            int pos = basew + incl - cnt;
#pragma unroll
            for (int j = 0; j < 8; j++) {
                if (v[j]) g_ve[pos++] = make_int2(sv[j], dv[j]);
            }
        }
    } else {
        // ---- encode: token histogram + X@w1+b1 (UNSCALED) ----
        float* s_emb = reinterpret_cast<float*>(dsm);      // 96
        float* s_w1  = s_emb + 96;                         // 272
        float* s_b1  = s_w1 + 272;                         // 16
        for (int j = t; j < 96; j += H_THREADS)  s_emb[j] = embed[j];
        for (int j = t; j < 272; j += H_THREADS) s_w1[j]  = w1[j];
        if (t < 16) s_b1[t] = b1[t];
        __syncthreads();

        for (int n = base_t; n < NND; n += H_HALF_TH) {
            int c1 = 0, c2 = 0, c3 = 0, c4 = 0, c5 = 0;
            const V8* tp = reinterpret_cast<const V8*>(seq + (long)n * LTOK);
#pragma unroll
            for (int i = 0; i < 8; i++) {
                V8 v = ldg256u(tp + i);
                int tok[8] = {(int)v.a.x, (int)v.a.y, (int)v.a.z, (int)v.a.w,
                              (int)v.b.x, (int)v.b.y, (int)v.b.z, (int)v.b.w};
#pragma unroll
                for (int j = 0; j < 8; j++) {
                    int tk = tok[j];
                    c1 += (tk == 1); c2 += (tk == 2); c3 += (tk == 3);
                    c4 += (tk == 4); c5 += (tk == 5);
                }
            }
            int nz = c1 + c2 + c3 + c4 + c5;
            float inv = 1.0f / fmaxf((float)nz, 1.0f);
            float f1 = c1 * inv, f2 = c2 * inv, f3 = c3 * inv, f4 = c4 * inv, f5 = c5 * inv;

            float x[17];
#pragma unroll
            for (int k = 0; k < 16; k++) {
                x[k] = f1 * s_emb[16 + k] + f2 * s_emb[32 + k] + f3 * s_emb[48 + k]
                     + f4 * s_emb[64 + k] + f5 * s_emb[80 + k];
            }
            x[16] = xcov[n];

            float m[16];
#pragma unroll
            for (int k = 0; k < 16; k++) {
                float s = s_b1[k];
#pragma unroll
                for (int j = 0; j < 17; j++) s += x[j] * s_w1[j * 16 + k];
                m[k] = s;   // UNSCALED
            }
            stg256f(&g_Ms1[2 * n + 0], m);
            stg256f(&g_Ms1[2 * n + 1], m + 8);
        }
    }
}

// ---------------- K2: persistent middle (dinv/zero -> agg1 -> fin1 -> agg2 -> fin2) ----------------
#define PB 148
#define PT 512
#define PTH (PB * PT)

__device__ __forceinline__ void grid_barrier() {
    __syncthreads();
    if (threadIdx.x == 0) {
        unsigned old = g_gen;
        __threadfence();
        unsigned a = atomicAdd(&g_arrive, 1);
        if (a == PB - 1) {
            g_arrive = 0;
            __threadfence();
            g_gen = old + 1;
        } else {
            while (g_gen == old) __nanosleep(64);
            __threadfence();
        }
    }
    __syncthreads();
}

__global__ void __launch_bounds__(PT, 1) k_mid(
    const float* __restrict__ w2, const float* __restrict__ b2,
    const float* __restrict__ we1, const float* __restrict__ be1)
{
    __shared__ float s_w2[256];
    __shared__ float s_b2[16];
    __shared__ float s_we1[512];
    __shared__ float s_eb1[16];
    const int t = threadIdx.x;
    const int gtid = blockIdx.x * PT + t;

    for (int j = t; j < 256; j += PT) s_w2[j] = w2[j];
    for (int j = t; j < 512; j += PT) s_we1[j] = we1[j];
    if (t < 16) { s_b2[t] = b2[t]; s_eb1[t] = be1[t]; }
    __syncthreads();

    // ---- P0: dinv + zero aggs ----
    {
        float zr[8] = {0.f,0.f,0.f,0.f,0.f,0.f,0.f,0.f};
        for (int n = gtid; n < NND; n += PTH) {
            g_dinv[n] = rsqrtf((float)g_deg[n] + 1.0f + 1e-8f);
            stg256f(&g_agg1[2 * n + 0], zr);
            stg256f(&g_agg1[2 * n + 1], zr);
            stg256f(&g_agg2[2 * n + 0], zr);
            stg256f(&g_agg2[2 * n + 1], zr);
        }
    }
    grid_barrier();

    // ---- P1: aggregate layer 1 (dinv[dst]-weighted, Ms1 unscaled) ----
    {
        int cnt = g_vcnt;
        int npair = (cnt + 1) >> 1;
        for (int i = gtid; i < npair; i += PTH) {
            int4 e2 = *reinterpret_cast<const int4*>(&g_ve[2 * i]);
            bool second = (2 * i + 1 < cnt);
            float c0 = __ldg(&g_dinv[e2.y]);
            F8 r0a = ldg256f(&g_Ms1[2 * e2.y + 0]);
            F8 r0b = ldg256f(&g_Ms1[2 * e2.y + 1]);
            float c1 = 0.f;
            F8 r1a, r1b;
            if (second) {
                c1 = __ldg(&g_dinv[e2.w]);
                r1a = ldg256f(&g_Ms1[2 * e2.w + 0]);
                r1b = ldg256f(&g_Ms1[2 * e2.w + 1]);
            }
            float* ap0 = (float*)g_agg1 + e2.x * 16;
            float4 v;
            v = r0a.a; v.x*=c0; v.y*=c0; v.z*=c0; v.w*=c0; red_add_v4(ap0 + 0,  v);
            v = r0a.b; v.x*=c0; v.y*=c0; v.z*=c0; v.w*=c0; red_add_v4(ap0 + 4,  v);
            v = r0b.a; v.x*=c0; v.y*=c0; v.z*=c0; v.w*=c0; red_add_v4(ap0 + 8,  v);
            v = r0b.b; v.x*=c0; v.y*=c0; v.z*=c0; v.w*=c0; red_add_v4(ap0 + 12, v);
            if (second) {
                float* ap1 = (float*)g_agg1 + e2.z * 16;
                v = r1a.a; v.x*=c1; v.y*=c1; v.z*=c1; v.w*=c1; red_add_v4(ap1 + 0,  v);
                v = r1a.b; v.x*=c1; v.y*=c1; v.z*=c1; v.w*=c1; red_add_v4(ap1 + 4,  v);
                v = r1b.a; v.x*=c1; v.y*=c1; v.z*=c1; v.w*=c1; red_add_v4(ap1 + 8,  v);
                v = r1b.b; v.x*=c1; v.y*=c1; v.z*=c1; v.w*=c1; red_add_v4(ap1 + 12, v);
            }
        }
    }
    grid_barrier();

    // ---- P2: fin1: h = relu(dinv*agg1 + dinv^2*M1); Ms2 = dinv*(h@w2+b2) ----
    for (int n = gtid; n < NND; n += PTH) {
        float dinv = g_dinv[n];
        float d2 = dinv * dinv;
        float4 a0 = ldcg128(reinterpret_cast<const float4*>(&g_agg1[2 * n + 0]) + 0);
        float4 a1 = ldcg128(reinterpret_cast<const float4*>(&g_agg1[2 * n + 0]) + 1);
        float4 a2 = ldcg128(reinterpret_cast<const float4*>(&g_agg1[2 * n + 1]) + 0);
        float4 a3 = ldcg128(reinterpret_cast<const float4*>(&g_agg1[2 * n + 1]) + 1);
        F8 ma = ldg256f(&g_Ms1[2 * n + 0]);
        F8 mb = ldg256f(&g_Ms1[2 * n + 1]);
        float av[16] = {a0.x,a0.y,a0.z,a0.w, a1.x,a1.y,a1.z,a1.w,
                        a2.x,a2.y,a2.z,a2.w, a3.x,a3.y,a3.z,a3.w};
        const float* mv0 = reinterpret_cast<const float*>(&ma);
        const float* mv1 = reinterpret_cast<const float*>(&mb);
        float h[16];
#pragma unroll
        for (int k = 0; k < 8; k++) h[k] = fmaxf(dinv * av[k] + d2 * mv0[k], 0.f);
#pragma unroll
        for (int k = 0; k < 8; k++) h[8 + k] = fmaxf(dinv * av[8 + k] + d2 * mv1[k], 0.f);
        float m2[16];
#pragma unroll
        for (int k = 0; k < 16; k++) {
            float s = s_b2[k];
#pragma unroll
            for (int j = 0; j < 16; j++) s += h[j] * s_w2[j * 16 + k];
            m2[k] = s * dinv;   // pre-scaled
        }
        stg256f(&g_Ms2[2 * n + 0], m2);
        stg256f(&g_Ms2[2 * n + 1], m2 + 8);
    }
    grid_barrier();

    // ---- P3: aggregate layer 2 (Ms2 pre-scaled) ----
    {
        int cnt = g_vcnt;
        int npair = (cnt + 1) >> 1;
        for (int i = gtid; i < npair; i += PTH) {
            int4 e2 = *reinterpret_cast<const int4*>(&g_ve[2 * i]);
            bool second = (2 * i + 1 < cnt);
            F8 r0a = ldg256f(&g_Ms2[2 * e2.y + 0]);
            F8 r0b = ldg256f(&g_Ms2[2 * e2.y + 1]);
            F8 r1a, r1b;
            if (second) {
                r1a = ldg256f(&g_Ms2[2 * e2.w + 0]);
                r1b = ldg256f(&g_Ms2[2 * e2.w + 1]);
            }
            float* ap0 = (float*)g_agg2 + e2.x * 16;
            red_add_v4(ap0 + 0,  r0a.a);
            red_add_v4(ap0 + 4,  r0a.b);
            red_add_v4(ap0 + 8,  r0b.a);
            red_add_v4(ap0 + 12, r0b.b);
            if (second) {
                float* ap1 = (float*)g_agg2 + e2.z * 16;
                red_add_v4(ap1 + 0,  r1a.a);
                red_add_v4(ap1 + 4,  r1a.b);
                red_add_v4(ap1 + 8,  r1b.a);
                red_add_v4(ap1 + 12, r1b.b);
            }
        }
    }
    grid_barrier();

    // ---- P4: fin2 -> A,B fp16 ----
    for (int n = gtid; n < NND; n += PTH) {
        float dinv = g_dinv[n];
        float4 a0 = ldcg128(reinterpret_cast<const float4*>(&g_agg2[2 * n + 0]) + 0);
        float4 a1 = ldcg128(reinterpret_cast<const float4*>(&g_agg2[2 * n + 0]) + 1);
        float4 a2 = ldcg128(reinterpret_cast<const float4*>(&g_agg2[2 * n + 1]) + 0);
        float4 a3 = ldcg128(reinterpret_cast<const float4*>(&g_agg2[2 * n + 1]) + 1);
        F8 ma = ldg256f(&g_Ms2[2 * n + 0]);
        F8 mb = ldg256f(&g_Ms2[2 * n + 1]);
        float agv[16] = {a0.x,a0.y,a0.z,a0.w, a1.x,a1.y,a1.z,a1.w,
                         a2.x,a2.y,a2.z,a2.w, a3.x,a3.y,a3.z,a3.w};
        const float* mv0 = reinterpret_cast<const float*>(&ma);
        const float* mv1 = reinterpret_cast<const float*>(&mb);
        float h[16];
#pragma unroll
        for (int k = 0; k < 8; k++) h[k] = fmaxf(dinv * (agv[k] + mv0[k]), 0.f);
#pragma unroll
        for (int k = 0; k < 8; k++) h[8 + k] = fmaxf(dinv * (agv[8 + k] + mv1[k]), 0.f);
        float av[16], bv[16];
#pragma unroll
        for (int k = 0; k < 16; k++) {
            float sa = s_eb1[k];
            float sbv = 0.f;
#pragma unroll
            for (int j = 0; j < 16; j++) {
                sa  += h[j] * s_we1[j * 16 + k];
                sbv += h[j] * s_we1[(16 + j) * 16 + k];
            }
            av[k] = sa; bv[k] = sbv;
        }
        unsigned wa[8], wb[8];
#pragma unroll
        for (int i = 0; i < 8; i++) {
            __half2 pa = __floats2half2_rn(av[2 * i], av[2 * i + 1]);
            __half2 pb = __floats2half2_rn(bv[2 * i], bv[2 * i + 1]);
            wa[i] = *reinterpret_cast<unsigned*>(&pa);
            wb[i] = *reinterpret_cast<unsigned*>(&pb);
        }
        stg256u(&g_Ah[n], wa);
        stg256u(&g_Bh[n], wb);
    }
}

// ---------------- K3: edge MLP output (4 edges/thread, v8 gathers) ----------------
__global__ void k_edge_out(const int* __restrict__ ei, const float* __restrict__ eattr,
                           const float* __restrict__ we1, const float* __restrict__ we2,
                           const float* __restrict__ be2, float* __restrict__ out) {
    __shared__ float sWc[5 * 16];
    __shared__ float sW2[16];
    __shared__ float sb2;
    int t = threadIdx.x;
    for (int j = t; j < 80; j += blockDim.x) sWc[j] = we1[32 * 16 + j];
    if (t < 16) sW2[t] = we2[t];
    if (t == 0) sb2 = be2[0];
    __syncthreads();

    int gt = blockIdx.x * blockDim.x + t;
    int base_e = gt * 4;
    int4 s4 = *reinterpret_cast<const int4*>(ei + base_e);
    int4 d4 = *reinterpret_cast<const int4*>(ei + NE + base_e);
    int sv[4] = {s4.x, s4.y, s4.z, s4.w};
    int dv[4] = {d4.x, d4.y, d4.z, d4.w};

    V8 pa[2], pb[2];
#pragma unroll
    for (int j = 0; j < 2; j++) {
        pa[j] = ldg256u(&g_Ah[sv[j]]);
        pb[j] = ldg256u(&g_Bh[dv[j]]);
    }
    float ea[20];
    const float4* ep = reinterpret_cast<const float4*>(eattr + (long)base_e * EF);
#pragma unroll
    for (int i = 0; i < 5; i++) {
        float4 v = ep[i];
        ea[4 * i + 0] = v.x; ea[4 * i + 1] = v.y; ea[4 * i + 2] = v.z; ea[4 * i + 3] = v.w;
    }

    float res[4];
#pragma unroll
    for (int p = 0; p < 2; p++) {
        if (p == 1) {
#pragma unroll
            for (int j = 0; j < 2; j++) {
                pa[j] = ldg256u(&g_Ah[sv[2 + j]]);
                pb[j] = ldg256u(&g_Bh[dv[2 + j]]);
            }
        }
#pragma unroll
        for (int q = 0; q < 2; q++) {
            int j = 2 * p + q;
            unsigned aw[8] = {pa[q].a.x, pa[q].a.y, pa[q].a.z, pa[q].a.w,
                              pa[q].b.x, pa[q].b.y, pa[q].b.z, pa[q].b.w};
            unsigned bw[8] = {pb[q].a.x, pb[q].a.y, pb[q].a.z, pb[q].a.w,
                              pb[q].b.x, pb[q].b.y, pb[q].b.z, pb[q].b.w};
            float h[16];
#pragma unroll
            for (int i = 0; i < 8; i++) {
                float2 fa = __half22float2(*reinterpret_cast<__half2*>(&aw[i]));
                float2 fb = __half22float2(*reinterpret_cast<__half2*>(&bw[i]));
                h[2 * i + 0] = fa.x + fb.x;
                h[2 * i + 1] = fa.y + fb.y;
            }
#pragma unroll
            for (int r = 0; r < EF; r++) {
                float eav = ea[5 * j + r];
#pragma unroll
                for (int k = 0; k < 16; k++) h[k] += eav * sWc[r * 16 + k];
            }
            float acc = sb2;
#pragma unroll
            for (int k = 0; k < 16; k++) acc += fmaxf(h[k], 0.f) * sW2[k];
            res[j] = acc;
        }
    }
    *reinterpret_cast<float4*>(out + base_e) = make_float4(res[0], res[1], res[2], res[3]);
}

extern "C" void kernel_launch(void* const* d_in, const int* in_sizes, int n_in,
                              void* d_out, int out_size) {
    const int*   seq   = (const int*)d_in[0];
    const float* xcov  = (const float*)d_in[1];
    const int*   ei    = (const int*)d_in[2];
    const float* eattr = (const float*)d_in[3];
    const int*   batch = (const int*)d_in[4];
    const float* embed = (const float*)d_in[5];
    const float* w1    = (const float*)d_in[6];
    const float* b1    = (const float*)d_in[7];
    const float* w2    = (const float*)d_in[8];
    const float* b2    = (const float*)d_in[9];
    const float* we1   = (const float*)d_in[10];
    const float* be1   = (const float*)d_in[11];
    const float* we2   = (const float*)d_in[12];
    const float* be2   = (const float*)d_in[13];
    float* out = (float*)d_out;

    static bool attr_set = false;
    if (!attr_set) {
        cudaFuncSetAttribute((const void*)k_deg_encode,
                             cudaFuncAttributeMaxDynamicSharedMemorySize, NND);
        attr_set = true;
    }

    const int TB = 256;
    const int nb_e4 = NE / (TB * 4);
    const int nb_n = (NND + TB - 1) / TB;

    k_prep<<<nb_n, TB>>>(batch);
    k_deg_encode<<<H_BLOCKS, H_THREADS, NND>>>(ei, seq, xcov, embed, w1, b1);
    k_mid<<<PB, PT>>>(w2, b2, we1, be1);
    k_edge_out<<<nb_e4, TB>>>(ei, eattr, we1, we2, be2, out);
}

// round 10
// speedup vs baseline: 1.1540x; 1.1540x over previous
#include <cuda_runtime.h>
#include <cuda_fp16.h>
#include <math.h>

#define NND 100000
#define NE  3200000
#define LTOK 64
#define HID 16
#define EF  5

struct __align__(32) V8 { uint4 a, b; };
struct __align__(32) F8 { float4 a, b; };

// ---- scratch (device globals; no allocation allowed) ----
__device__ float g_dinv[NND];
__device__ int   g_deg[NND];
__device__ F8    g_Ms1[NND * 2];   // row n = [2n],[2n+1]; dinv*(X@w1+b1)
__device__ F8    g_Ms2[NND * 2];
__device__ F8    g_agg1[NND * 2];
__device__ F8    g_agg2[NND * 2];
__device__ V8    g_Ah[NND];        // A row = 16 half = 32B
__device__ V8    g_Bh[NND];
__device__ __align__(16) int2 g_ve[NE + 2];
__device__ __align__(16) unsigned char g_b8[NND];  // batch as uint8 (64 graphs)
__device__ int   g_vcnt;

__device__ __forceinline__ void red_add_v4(float* p, float4 v) {
    asm volatile("red.global.add.v4.f32 [%0], {%1, %2, %3, %4};"
                 :: "l"(p), "f"(v.x), "f"(v.y), "f"(v.z), "f"(v.w) : "memory");
}
__device__ __forceinline__ V8 ldg256u(const V8* p) {
    V8 r;
    asm volatile("ld.global.nc.v8.b32 {%0,%1,%2,%3,%4,%5,%6,%7}, [%8];"
        : "=r"(r.a.x), "=r"(r.a.y), "=r"(r.a.z), "=r"(r.a.w),
          "=r"(r.b.x), "=r"(r.b.y), "=r"(r.b.z), "=r"(r.b.w)
        : "l"(p));
    return r;
}
__device__ __forceinline__ F8 ldg256f(const F8* p) {
    F8 r;
    asm volatile("ld.global.nc.v8.f32 {%0,%1,%2,%3,%4,%5,%6,%7}, [%8];"
        : "=f"(r.a.x), "=f"(r.a.y), "=f"(r.a.z), "=f"(r.a.w),
          "=f"(r.b.x), "=f"(r.b.y), "=f"(r.b.z), "=f"(r.b.w)
        : "l"(p));
    return r;
}
__device__ __forceinline__ void stg256f(F8* p, const float* v) {
    asm volatile("st.global.v8.f32 [%0], {%1,%2,%3,%4,%5,%6,%7,%8};"
        :: "l"(p), "f"(v[0]), "f"(v[1]), "f"(v[2]), "f"(v[3]),
           "f"(v[4]), "f"(v[5]), "f"(v[6]), "f"(v[7]) : "memory");
}
__device__ __forceinline__ void stg256u(V8* p, const unsigned* v) {
    asm volatile("st.global.v8.b32 [%0], {%1,%2,%3,%4,%5,%6,%7,%8};"
        :: "l"(p), "r"(v[0]), "r"(v[1]), "r"(v[2]), "r"(v[3]),
           "r"(v[4]), "r"(v[5]), "r"(v[6]), "r"(v[7]) : "memory");
}

// ---------------- K0: zero degree + counter + pack batch->u8 ----------------
__global__ void k_zero_small(const int* __restrict__ batch) {
    int i = blockIdx.x * blockDim.x + threadIdx.x;
    if (i < NND) {
        g_deg[i] = 0;
        g_b8[i] = (unsigned char)batch[i];
    }
    if (i == 0) g_vcnt = 0;
}

// ---------------- K1: degree + valid-edge compaction via smem batch table ----------------
#define DC_BLOCKS 296
#define DC_THREADS 512
__global__ void __launch_bounds__(DC_THREADS) k_deg_compact(const int* __restrict__ ei) {
    extern __shared__ unsigned char s_b8[];   // NND bytes (100000)
    {
        const int4* src = reinterpret_cast<const int4*>(g_b8);
        int4* dst = reinterpret_cast<int4*>(s_b8);
        for (int j = threadIdx.x; j < NND / 16; j += DC_THREADS) dst[j] = src[j];
    }
    __syncthreads();

    const int NCH = NE / 8;                       // 400000 chunks of 8 edges
    const int STRIDE = DC_BLOCKS * DC_THREADS;    // 151552
    const int ITERS = (NCH + STRIDE - 1) / STRIDE; // 3
    int gtid = blockIdx.x * DC_THREADS + threadIdx.x;
    int lane = threadIdx.x & 31;

    for (int it = 0; it < ITERS; it++) {
        int i = gtid + it * STRIDE;
        bool active = (i < NCH);
        int sv[8], dv[8];
        bool v[8];
        int cnt = 0;
        if (active) {
            int base_e = i * 8;
            V8 sa = ldg256u(reinterpret_cast<const V8*>(ei + base_e));
            V8 da = ldg256u(reinterpret_cast<const V8*>(ei + NE + base_e));
            sv[0]=sa.a.x; sv[1]=sa.a.y; sv[2]=sa.a.z; sv[3]=sa.a.w;
            sv[4]=sa.b.x; sv[5]=sa.b.y; sv[6]=sa.b.z; sv[7]=sa.b.w;
            dv[0]=da.a.x; dv[1]=da.a.y; dv[2]=da.a.z; dv[3]=da.a.w;
            dv[4]=da.b.x; dv[5]=da.b.y; dv[6]=da.b.z; dv[7]=da.b.w;
#pragma unroll
            for (int j = 0; j < 8; j++) {
                v[j] = (s_b8[sv[j]] == s_b8[dv[j]]);
                if (v[j]) { atomicAdd(&g_deg[sv[j]], 1); cnt++; }
            }
        } else {
#pragma unroll
            for (int j = 0; j < 8; j++) v[j] = false;
        }
        int incl = cnt;
#pragma unroll
        for (int off = 1; off < 32; off <<= 1) {
            int nv = __shfl_up_sync(0xffffffffu, incl, off);
            if (lane >= off) incl += nv;
        }
        int total = __shfl_sync(0xffffffffu, incl, 31);
        int basew = 0;
        if (lane == 31 && total > 0) basew = atomicAdd(&g_vcnt, total);
        basew = __shfl_sync(0xffffffffu, basew, 31);
        int pos = basew + incl - cnt;
#pragma unroll
        for (int j = 0; j < 8; j++) {
            if (v[j]) g_ve[pos++] = make_int2(sv[j], dv[j]);
        }
    }
}

// ---------------- K2: encode nodes (token histogram) + dinv + Ms1; zero agg1 ----------------
__global__ void k_encode(const int* __restrict__ seq, const float* __restrict__ xcov,
                         const float* __restrict__ embed, const float* __restrict__ w1,
                         const float* __restrict__ b1) {
    __shared__ float s_emb[6 * 16];
    __shared__ float s_w1[17 * 16];
    __shared__ float s_b1[16];
    int t = threadIdx.x;
    for (int j = t; j < 96; j += blockDim.x) s_emb[j] = embed[j];
    for (int j = t; j < 272; j += blockDim.x) s_w1[j] = w1[j];
    if (t < 16) s_b1[t] = b1[t];
    __syncthreads();

    int n = blockIdx.x * blockDim.x + t;
    if (n >= NND) return;

    float dinv = rsqrtf((float)g_deg[n] + 1.0f + 1e-8f);
    g_dinv[n] = dinv;

    float zr[8] = {0.f,0.f,0.f,0.f,0.f,0.f,0.f,0.f};
    stg256f(&g_agg1[2 * n + 0], zr);
    stg256f(&g_agg1[2 * n + 1], zr);

    int c1 = 0, c2 = 0, c3 = 0, c4 = 0, c5 = 0;
    const V8* tp = reinterpret_cast<const V8*>(seq + (long)n * LTOK);
#pragma unroll
    for (int i = 0; i < 8; i++) {
        V8 v = ldg256u(tp + i);
        int tok[8] = {(int)v.a.x, (int)v.a.y, (int)v.a.z, (int)v.a.w,
                      (int)v.b.x, (int)v.b.y, (int)v.b.z, (int)v.b.w};
#pragma unroll
        for (int j = 0; j < 8; j++) {
            int tk = tok[j];
            c1 += (tk == 1); c2 += (tk == 2); c3 += (tk == 3);
            c4 += (tk == 4); c5 += (tk == 5);
        }
    }
    int nz = c1 + c2 + c3 + c4 + c5;
    float inv = 1.0f / fmaxf((float)nz, 1.0f);
    float f1 = c1 * inv, f2 = c2 * inv, f3 = c3 * inv, f4 = c4 * inv, f5 = c5 * inv;

    float x[17];
#pragma unroll
    for (int k = 0; k < 16; k++) {
        x[k] = f1 * s_emb[16 + k] + f2 * s_emb[32 + k] + f3 * s_emb[48 + k]
             + f4 * s_emb[64 + k] + f5 * s_emb[80 + k];
    }
    x[16] = xcov[n];

    float m[16];
#pragma unroll
    for (int k = 0; k < 16; k++) {
        float s = s_b1[k];
#pragma unroll
        for (int j = 0; j < 17; j++) s += x[j] * s_w1[j * 16 + k];
        m[k] = s * dinv;  // pre-scale by dinv
    }
    stg256f(&g_Ms1[2 * n + 0], m);
    stg256f(&g_Ms1[2 * n + 1], m + 8);
}

// ---------------- K3/K5: aggregation, 2 edges/thread, v8 row loads ----------------
template <int LAYER>
__global__ void k_aggregate() {
    int cnt = g_vcnt;
    int npair = (cnt + 1) >> 1;
    int stride = gridDim.x * blockDim.x;
    const F8* Ms = (LAYER == 0) ? g_Ms1 : g_Ms2;
    float* agg = (LAYER == 0) ? (float*)g_agg1 : (float*)g_agg2;
    for (int i = blockIdx.x * blockDim.x + threadIdx.x; i < npair; i += stride) {
        int4 e2 = *reinterpret_cast<const int4*>(&g_ve[2 * i]);
        bool second = (2 * i + 1 < cnt);
        F8 r0a = ldg256f(Ms + 2 * e2.y + 0);
        F8 r0b = ldg256f(Ms + 2 * e2.y + 1);
        F8 r1a, r1b;
        if (second) {
            r1a = ldg256f(Ms + 2 * e2.w + 0);
            r1b = ldg256f(Ms + 2 * e2.w + 1);
        }
        float* ap0 = agg + e2.x * 16;
        red_add_v4(ap0 + 0,  r0a.a);
        red_add_v4(ap0 + 4,  r0a.b);
        red_add_v4(ap0 + 8,  r0b.a);
        red_add_v4(ap0 + 12, r0b.b);
        if (second) {
            float* ap1 = agg + e2.z * 16;
            red_add_v4(ap1 + 0,  r1a.a);
            red_add_v4(ap1 + 4,  r1a.b);
            red_add_v4(ap1 + 8,  r1b.a);
            red_add_v4(ap1 + 12, r1b.b);
        }
    }
}

// ---------------- K4: H1 = relu(dinv*(agg1+Ms1)); Ms2 = dinv*(H1@w2+b2); zero agg2 ----------------
__global__ void k_finalize1(const float* __restrict__ w2, const float* __restrict__ b2) {
    __shared__ float sW[16 * 16];
    __shared__ float sb[16];
    int t = threadIdx.x;
    for (int j = t; j < 256; j += blockDim.x) sW[j] = w2[j];
    if (t < 16) sb[t] = b2[t];
    __syncthreads();

    int n = blockIdx.x * blockDim.x + t;
    if (n >= NND) return;
    float dinv = g_dinv[n];

    float zr[8] = {0.f,0.f,0.f,0.f,0.f,0.f,0.f,0.f};
    stg256f(&g_agg2[2 * n + 0], zr);
    stg256f(&g_agg2[2 * n + 1], zr);

    F8 aa = ldg256f(&g_agg1[2 * n + 0]);
    F8 ab = ldg256f(&g_agg1[2 * n + 1]);
    F8 ma = ldg256f(&g_Ms1[2 * n + 0]);
    F8 mb = ldg256f(&g_Ms1[2 * n + 1]);
    const float* av = reinterpret_cast<const float*>(&aa);
    const float* mv = reinterpret_cast<const float*>(&ma);
    float h[16];
#pragma unroll
    for (int k = 0; k < 8; k++) h[k] = fmaxf(dinv * (av[k] + mv[k]), 0.f);
    const float* av2 = reinterpret_cast<const float*>(&ab);
    const float* mv2 = reinterpret_cast<const float*>(&mb);
#pragma unroll
    for (int k = 0; k < 8; k++) h[8 + k] = fmaxf(dinv * (av2[k] + mv2[k]), 0.f);

    float m2[16];
#pragma unroll
    for (int k = 0; k < 16; k++) {
        float s = sb[k];
#pragma unroll
        for (int j = 0; j < 16; j++) s += h[j] * sW[j * 16 + k];
        m2[k] = s * dinv;  // pre-scale
    }
    stg256f(&g_Ms2[2 * n + 0], m2);
    stg256f(&g_Ms2[2 * n + 1], m2 + 8);
}

// ---------------- K6: H2 -> A,B stored fp16 (v8 store) ----------------
__global__ void k_finalize2(const float* __restrict__ we1, const float* __restrict__ be1) {
    __shared__ float sW[32 * 16];
    __shared__ float sb[16];
    int t = threadIdx.x;
    for (int j = t; j < 512; j += blockDim.x) sW[j] = we1[j];
    if (t < 16) sb[t] = be1[t];
    __syncthreads();

    int n = blockIdx.x * blockDim.x + t;
    if (n >= NND) return;
    float dinv = g_dinv[n];
    F8 aa = ldg256f(&g_agg2[2 * n + 0]);
    F8 ab = ldg256f(&g_agg2[2 * n + 1]);
    F8 ma = ldg256f(&g_Ms2[2 * n + 0]);
    F8 mb = ldg256f(&g_Ms2[2 * n + 1]);
    const float* av0 = reinterpret_cast<const float*>(&aa);
    const float* mv0 = reinterpret_cast<const float*>(&ma);
    const float* av1 = reinterpret_cast<const float*>(&ab);
    const float* mv1 = reinterpret_cast<const float*>(&mb);
    float h[16];
#pragma unroll
    for (int k = 0; k < 8; k++) h[k] = fmaxf(dinv * (av0[k] + mv0[k]), 0.f);
#pragma unroll
    for (int k = 0; k < 8; k++) h[8 + k] = fmaxf(dinv * (av1[k] + mv1[k]), 0.f);

    float av[16], bv[16];
#pragma unroll
    for (int k = 0; k < 16; k++) {
        float sa = sb[k];
        float sbv = 0.f;
#pragma unroll
        for (int j = 0; j < 16; j++) {
            sa  += h[j] * sW[j * 16 + k];
            sbv += h[j] * sW[(16 + j) * 16 + k];
        }
        av[k] = sa; bv[k] = sbv;
    }
    unsigned wa[8], wb[8];
#pragma unroll
    for (int i = 0; i < 8; i++) {
        __half2 pa = __floats2half2_rn(av[2 * i], av[2 * i + 1]);
        __half2 pb = __floats2half2_rn(bv[2 * i], bv[2 * i + 1]);
        wa[i] = *reinterpret_cast<unsigned*>(&pa);
        wb[i] = *reinterpret_cast<unsigned*>(&pb);
    }
    stg256u(&g_Ah[n], wa);
    stg256u(&g_Bh[n], wb);
}

// ---------------- K7: edge MLP output (2 edges/thread, reg-capped for 50% occ) ----------------
#define EO_TB 256
__global__ void __launch_bounds__(EO_TB, 4) k_edge_out(
    const int* __restrict__ ei, const float* __restrict__ eattr,
    const float* __restrict__ we1, const float* __restrict__ we2,
    const float* __restrict__ be2, float* __restrict__ out) {
    __shared__ float sWc[5 * 16];  // we1 rows 32..36
    __shared__ float sW2[16];
    __shared__ float sb2;
    int t = threadIdx.x;
    for (int j = t; j < 80; j += EO_TB) sWc[j] = we1[32 * 16 + j];
    if (t < 16) sW2[t] = we2[t];
    if (t == 0) sb2 = be2[0];
    __syncthreads();

    int gt = blockIdx.x * EO_TB + t;
    int base_e = gt * 2;                       // NE % (2*256) == 0
    int2 s2 = *reinterpret_cast<const int2*>(ei + base_e);
    int2 d2 = *reinterpret_cast<const int2*>(ei + NE + base_e);

    V8 pa0 = ldg256u(&g_Ah[s2.x]);
    V8 pb0 = ldg256u(&g_Bh[d2.x]);
    V8 pa1 = ldg256u(&g_Ah[s2.y]);
    V8 pb1 = ldg256u(&g_Bh[d2.y]);

    // 10 eattr floats (8B-aligned: base_e*5*4 = gt*40)
    float ea[10];
    const float2* ep = reinterpret_cast<const float2*>(eattr + (long)base_e * EF);
#pragma unroll
    for (int q = 0; q < 5; q++) {
        float2 v = ep[q];
        ea[2 * q + 0] = v.x;
        ea[2 * q + 1] = v.y;
    }

    float res[2];
#pragma unroll
    for (int j = 0; j < 2; j++) {
        const V8& PA = j ? pa1 : pa0;
        const V8& PB = j ? pb1 : pb0;
        unsigned aw[8] = {PA.a.x, PA.a.y, PA.a.z, PA.a.w, PA.b.x, PA.b.y, PA.b.z, PA.b.w};
        unsigned bw[8] = {PB.a.x, PB.a.y, PB.a.z, PB.a.w, PB.b.x, PB.b.y, PB.b.z, PB.b.w};
        float h[16];
#pragma unroll
        for (int i = 0; i < 8; i++) {
            float2 fa = __half22float2(*reinterpret_cast<__half2*>(&aw[i]));
            float2 fb = __half22float2(*reinterpret_cast<__half2*>(&bw[i]));
            h[2 * i + 0] = fa.x + fb.x;
            h[2 * i + 1] = fa.y + fb.y;
        }
#pragma unroll
        for (int r = 0; r < EF; r++) {
            float eav = ea[5 * j + r];
#pragma unroll
            for (int k = 0; k < 16; k++) h[k] += eav * sWc[r * 16 + k];
        }
        float acc = sb2;
#pragma unroll
        for (int k = 0; k < 16; k++) acc += fmaxf(h[k], 0.f) * sW2[k];
        res[j] = acc;
    }
    *reinterpret_cast<float2*>(out + base_e) = make_float2(res[0], res[1]);
}

extern "C" void kernel_launch(void* const* d_in, const int* in_sizes, int n_in,
                              void* d_out, int out_size) {
    const int*   seq   = (const int*)d_in[0];
    const float* xcov  = (const float*)d_in[1];
    const int*   ei    = (const int*)d_in[2];
    const float* eattr = (const float*)d_in[3];
    const int*   batch = (const int*)d_in[4];
    const float* embed = (const float*)d_in[5];
    const float* w1    = (const float*)d_in[6];
    const float* b1    = (const float*)d_in[7];
    const float* w2    = (const float*)d_in[8];
    const float* b2    = (const float*)d_in[9];
    const float* we1   = (const float*)d_in[10];
    const float* be1   = (const float*)d_in[11];
    const float* we2   = (const float*)d_in[12];
    const float* be2   = (const float*)d_in[13];
    float* out = (float*)d_out;

    static bool attr_set = false;
    if (!attr_set) {
        cudaFuncSetAttribute((const void*)k_deg_compact,
                             cudaFuncAttributeMaxDynamicSharedMemorySize, NND);
        attr_set = true;
    }

    const int TB = 256;
    const int nb_e2 = NE / (EO_TB * 2);           // 6250
    const int nb_n = (NND + TB - 1) / TB;

    k_zero_small<<<nb_n, TB>>>(batch);
    k_deg_compact<<<DC_BLOCKS, DC_THREADS, NND>>>(ei);
    k_encode<<<nb_n, TB>>>(seq, xcov, embed, w1, b1);
    k_aggregate<0><<<256, TB>>>();
    k_finalize1<<<nb_n, TB>>>(w2, b2);
    k_aggregate<1><<<256, TB>>>();
    k_finalize2<<<nb_n, TB>>>(we1, be1);
    k_edge_out<<<nb_e2, EO_TB>>>(ei, eattr, we1, we2, be2, out);
}

// round 11
// speedup vs baseline: 1.2504x; 1.0836x over previous
#include <cuda_runtime.h>
#include <cuda_fp16.h>
#include <math.h>

#define NND 100000
#define NE  3200000
#define LTOK 64
#define HID 16
#define EF  5

struct __align__(32) V8 { uint4 a, b; };
struct __align__(32) F8 { float4 a, b; };

// ---- scratch (device globals; no allocation allowed) ----
__device__ float g_dinv[NND];
__device__ int   g_deg[NND];
__device__ F8    g_Ms1[NND * 2];   // row n = [2n],[2n+1]; dinv*(X@w1+b1)
__device__ F8    g_Ms2[NND * 2];
__device__ F8    g_agg1[NND * 2];
__device__ F8    g_agg2[NND * 2];
__device__ V8    g_Ah[NND];        // A row = 16 half = 32B
__device__ V8    g_Bh[NND];
__device__ __align__(16) int2 g_ve[NE + 2];
__device__ __align__(16) unsigned char g_b8[NND];  // batch as uint8 (64 graphs)
__device__ int   g_vcnt;

__device__ __forceinline__ void red_add_v4(float* p, float4 v) {
    asm volatile("red.global.add.v4.f32 [%0], {%1, %2, %3, %4};"
                 :: "l"(p), "f"(v.x), "f"(v.y), "f"(v.z), "f"(v.w) : "memory");
}
__device__ __forceinline__ V8 ldg256u(const V8* p) {
    V8 r;
    asm volatile("ld.global.nc.v8.b32 {%0,%1,%2,%3,%4,%5,%6,%7}, [%8];"
        : "=r"(r.a.x), "=r"(r.a.y), "=r"(r.a.z), "=r"(r.a.w),
          "=r"(r.b.x), "=r"(r.b.y), "=r"(r.b.z), "=r"(r.b.w)
        : "l"(p));
    return r;
}
__device__ __forceinline__ F8 ldg256f(const F8* p) {
    F8 r;
    asm volatile("ld.global.nc.v8.f32 {%0,%1,%2,%3,%4,%5,%6,%7}, [%8];"
        : "=f"(r.a.x), "=f"(r.a.y), "=f"(r.a.z), "=f"(r.a.w),
          "=f"(r.b.x), "=f"(r.b.y), "=f"(r.b.z), "=f"(r.b.w)
        : "l"(p));
    return r;
}
__device__ __forceinline__ void stg256f(F8* p, const float* v) {
    asm volatile("st.global.v8.f32 [%0], {%1,%2,%3,%4,%5,%6,%7,%8};"
        :: "l"(p), "f"(v[0]), "f"(v[1]), "f"(v[2]), "f"(v[3]),
           "f"(v[4]), "f"(v[5]), "f"(v[6]), "f"(v[7]) : "memory");
}
__device__ __forceinline__ void stg256u(V8* p, const unsigned* v) {
    asm volatile("st.global.v8.b32 [%0], {%1,%2,%3,%4,%5,%6,%7,%8};"
        :: "l"(p), "r"(v[0]), "r"(v[1]), "r"(v[2]), "r"(v[3]),
           "r"(v[4]), "r"(v[5]), "r"(v[6]), "r"(v[7]) : "memory");
}

// ---------------- K0: zero degree + counter + pack batch->u8 ----------------
__global__ void k_zero_small(const int* __restrict__ batch) {
    int i = blockIdx.x * blockDim.x + threadIdx.x;
    if (i < NND) {
        g_deg[i] = 0;
        g_b8[i] = (unsigned char)batch[i];
    }
    if (i == 0) g_vcnt = 0;
}

// ---------------- K1: degree + valid-edge compaction via smem batch table ----------------
#define DC_BLOCKS 296
#define DC_THREADS 512
__global__ void __launch_bounds__(DC_THREADS) k_deg_compact(const int* __restrict__ ei) {
    extern __shared__ unsigned char s_b8[];   // NND bytes (100000)
    {
        const int4* src = reinterpret_cast<const int4*>(g_b8);
        int4* dst = reinterpret_cast<int4*>(s_b8);
        for (int j = threadIdx.x; j < NND / 16; j += DC_THREADS) dst[j] = src[j];
    }
    __syncthreads();

    const int NCH = NE / 8;                       // 400000 chunks of 8 edges
    const int STRIDE = DC_BLOCKS * DC_THREADS;    // 151552
    const int ITERS = (NCH + STRIDE - 1) / STRIDE; // 3
    int gtid = blockIdx.x * DC_THREADS + threadIdx.x;
    int lane = threadIdx.x & 31;

    for (int it = 0; it < ITERS; it++) {
        int i = gtid + it * STRIDE;
        bool active = (i < NCH);
        int sv[8], dv[8];
        bool v[8];
        int cnt = 0;
        if (active) {
            int base_e = i * 8;
            V8 sa = ldg256u(reinterpret_cast<const V8*>(ei + base_e));
            V8 da = ldg256u(reinterpret_cast<const V8*>(ei + NE + base_e));
            sv[0]=sa.a.x; sv[1]=sa.a.y; sv[2]=sa.a.z; sv[3]=sa.a.w;
            sv[4]=sa.b.x; sv[5]=sa.b.y; sv[6]=sa.b.z; sv[7]=sa.b.w;
            dv[0]=da.a.x; dv[1]=da.a.y; dv[2]=da.a.z; dv[3]=da.a.w;
            dv[4]=da.b.x; dv[5]=da.b.y; dv[6]=da.b.z; dv[7]=da.b.w;
#pragma unroll
            for (int j = 0; j < 8; j++) {
                v[j] = (s_b8[sv[j]] == s_b8[dv[j]]);
                if (v[j]) { atomicAdd(&g_deg[sv[j]], 1); cnt++; }
            }
        } else {
#pragma unroll
            for (int j = 0; j < 8; j++) v[j] = false;
        }
        int incl = cnt;
#pragma unroll
        for (int off = 1; off < 32; off <<= 1) {
            int nv = __shfl_up_sync(0xffffffffu, incl, off);
            if (lane >= off) incl += nv;
        }
        int total = __shfl_sync(0xffffffffu, incl, 31);
        int basew = 0;
        if (lane == 31 && total > 0) basew = atomicAdd(&g_vcnt, total);
        basew = __shfl_sync(0xffffffffu, basew, 31);
        int pos = basew + incl - cnt;
#pragma unroll
        for (int j = 0; j < 8; j++) {
            if (v[j]) g_ve[pos++] = make_int2(sv[j], dv[j]);
        }
    }
}

// ---------------- K2: encode nodes (token histogram) + dinv + Ms1; zero agg1 ----------------
__global__ void k_encode(const int* __restrict__ seq, const float* __restrict__ xcov,
                         const float* __restrict__ embed, const float* __restrict__ w1,
                         const float* __restrict__ b1) {
    __shared__ float s_emb[6 * 16];
    __shared__ float s_w1[17 * 16];
    __shared__ float s_b1[16];
    int t = threadIdx.x;
    for (int j = t; j < 96; j += blockDim.x) s_emb[j] = embed[j];
    for (int j = t; j < 272; j += blockDim.x) s_w1[j] = w1[j];
    if (t < 16) s_b1[t] = b1[t];
    __syncthreads();

    int n = blockIdx.x * blockDim.x + t;
    if (n >= NND) return;

    float dinv = rsqrtf((float)g_deg[n] + 1.0f + 1e-8f);
    g_dinv[n] = dinv;

    float zr[8] = {0.f,0.f,0.f,0.f,0.f,0.f,0.f,0.f};
    stg256f(&g_agg1[2 * n + 0], zr);
    stg256f(&g_agg1[2 * n + 1], zr);

    int c1 = 0, c2 = 0, c3 = 0, c4 = 0, c5 = 0;
    const V8* tp = reinterpret_cast<const V8*>(seq + (long)n * LTOK);
#pragma unroll
    for (int i = 0; i < 8; i++) {
        V8 v = ldg256u(tp + i);
        int tok[8] = {(int)v.a.x, (int)v.a.y, (int)v.a.z, (int)v.a.w,
                      (int)v.b.x, (int)v.b.y, (int)v.b.z, (int)v.b.w};
#pragma unroll
        for (int j = 0; j < 8; j++) {
            int tk = tok[j];
            c1 += (tk == 1); c2 += (tk == 2); c3 += (tk == 3);
            c4 += (tk == 4); c5 += (tk == 5);
        }
    }
    int nz = c1 + c2 + c3 + c4 + c5;
    float inv = 1.0f / fmaxf((float)nz, 1.0f);
    float f1 = c1 * inv, f2 = c2 * inv, f3 = c3 * inv, f4 = c4 * inv, f5 = c5 * inv;

    float x[17];
#pragma unroll
    for (int k = 0; k < 16; k++) {
        x[k] = f1 * s_emb[16 + k] + f2 * s_emb[32 + k] + f3 * s_emb[48 + k]
             + f4 * s_emb[64 + k] + f5 * s_emb[80 + k];
    }
    x[16] = xcov[n];

    float m[16];
#pragma unroll
    for (int k = 0; k < 16; k++) {
        float s = s_b1[k];
#pragma unroll
        for (int j = 0; j < 17; j++) s += x[j] * s_w1[j * 16 + k];
        m[k] = s * dinv;  // pre-scale by dinv
    }
    stg256f(&g_Ms1[2 * n + 0], m);
    stg256f(&g_Ms1[2 * n + 1], m + 8);
}

// ---------------- K3/K5: aggregation, 2 edges/thread, v8 row loads ----------------
template <int LAYER>
__global__ void k_aggregate() {
    int cnt = g_vcnt;
    int npair = (cnt + 1) >> 1;
    int stride = gridDim.x * blockDim.x;
    const F8* Ms = (LAYER == 0) ? g_Ms1 : g_Ms2;
    float* agg = (LAYER == 0) ? (float*)g_agg1 : (float*)g_agg2;
    for (int i = blockIdx.x * blockDim.x + threadIdx.x; i < npair; i += stride) {
        int4 e2 = *reinterpret_cast<const int4*>(&g_ve[2 * i]);
        bool second = (2 * i + 1 < cnt);
        F8 r0a = ldg256f(Ms + 2 * e2.y + 0);
        F8 r0b = ldg256f(Ms + 2 * e2.y + 1);
        F8 r1a, r1b;
        if (second) {
            r1a = ldg256f(Ms + 2 * e2.w + 0);
            r1b = ldg256f(Ms + 2 * e2.w + 1);
        }
        float* ap0 = agg + e2.x * 16;
        red_add_v4(ap0 + 0,  r0a.a);
        red_add_v4(ap0 + 4,  r0a.b);
        red_add_v4(ap0 + 8,  r0b.a);
        red_add_v4(ap0 + 12, r0b.b);
        if (second) {
            float* ap1 = agg + e2.z * 16;
            red_add_v4(ap1 + 0,  r1a.a);
            red_add_v4(ap1 + 4,  r1a.b);
            red_add_v4(ap1 + 8,  r1b.a);
            red_add_v4(ap1 + 12, r1b.b);
        }
    }
}

// ---------------- K4: H1 = relu(dinv*(agg1+Ms1)); Ms2 = dinv*(H1@w2+b2); zero agg2 ----------------
__global__ void k_finalize1(const float* __restrict__ w2, const float* __restrict__ b2) {
    __shared__ float sW[16 * 16];
    __shared__ float sb[16];
    int t = threadIdx.x;
    for (int j = t; j < 256; j += blockDim.x) sW[j] = w2[j];
    if (t < 16) sb[t] = b2[t];
    __syncthreads();

    int n = blockIdx.x * blockDim.x + t;
    if (n >= NND) return;
    float dinv = g_dinv[n];

    float zr[8] = {0.f,0.f,0.f,0.f,0.f,0.f,0.f,0.f};
    stg256f(&g_agg2[2 * n + 0], zr);
    stg256f(&g_agg2[2 * n + 1], zr);

    F8 aa = ldg256f(&g_agg1[2 * n + 0]);
    F8 ab = ldg256f(&g_agg1[2 * n + 1]);
    F8 ma = ldg256f(&g_Ms1[2 * n + 0]);
    F8 mb = ldg256f(&g_Ms1[2 * n + 1]);
    const float* av = reinterpret_cast<const float*>(&aa);
    const float* mv = reinterpret_cast<const float*>(&ma);
    float h[16];
#pragma unroll
    for (int k = 0; k < 8; k++) h[k] = fmaxf(dinv * (av[k] + mv[k]), 0.f);
    const float* av2 = reinterpret_cast<const float*>(&ab);
    const float* mv2 = reinterpret_cast<const float*>(&mb);
#pragma unroll
    for (int k = 0; k < 8; k++) h[8 + k] = fmaxf(dinv * (av2[k] + mv2[k]), 0.f);

    float m2[16];
#pragma unroll
    for (int k = 0; k < 16; k++) {
        float s = sb[k];
#pragma unroll
        for (int j = 0; j < 16; j++) s += h[j] * sW[j * 16 + k];
        m2[k] = s * dinv;  // pre-scale
    }
    stg256f(&g_Ms2[2 * n + 0], m2);
    stg256f(&g_Ms2[2 * n + 1], m2 + 8);
}

// ---------------- K6: H2 -> A,B stored fp16 (v8 store) ----------------
__global__ void k_finalize2(const float* __restrict__ we1, const float* __restrict__ be1) {
    __shared__ float sW[32 * 16];
    __shared__ float sb[16];
    int t = threadIdx.x;
    for (int j = t; j < 512; j += blockDim.x) sW[j] = we1[j];
    if (t < 16) sb[t] = be1[t];
    __syncthreads();

    int n = blockIdx.x * blockDim.x + t;
    if (n >= NND) return;
    float dinv = g_dinv[n];
    F8 aa = ldg256f(&g_agg2[2 * n + 0]);
    F8 ab = ldg256f(&g_agg2[2 * n + 1]);
    F8 ma = ldg256f(&g_Ms2[2 * n + 0]);
    F8 mb = ldg256f(&g_Ms2[2 * n + 1]);
    const float* av0 = reinterpret_cast<const float*>(&aa);
    const float* mv0 = reinterpret_cast<const float*>(&ma);
    const float* av1 = reinterpret_cast<const float*>(&ab);
    const float* mv1 = reinterpret_cast<const float*>(&mb);
    float h[16];
#pragma unroll
    for (int k = 0; k < 8; k++) h[k] = fmaxf(dinv * (av0[k] + mv0[k]), 0.f);
#pragma unroll
    for (int k = 0; k < 8; k++) h[8 + k] = fmaxf(dinv * (av1[k] + mv1[k]), 0.f);

    float av[16], bv[16];
#pragma unroll
    for (int k = 0; k < 16; k++) {
        float sa = sb[k];
        float sbv = 0.f;
#pragma unroll
        for (int j = 0; j < 16; j++) {
            sa  += h[j] * sW[j * 16 + k];
            sbv += h[j] * sW[(16 + j) * 16 + k];
        }
        av[k] = sa; bv[k] = sbv;
    }
    unsigned wa[8], wb[8];
#pragma unroll
    for (int i = 0; i < 8; i++) {
        __half2 pa = __floats2half2_rn(av[2 * i], av[2 * i + 1]);
        __half2 pb = __floats2half2_rn(bv[2 * i], bv[2 * i + 1]);
        wa[i] = *reinterpret_cast<unsigned*>(&pa);
        wb[i] = *reinterpret_cast<unsigned*>(&pb);
    }
    stg256u(&g_Ah[n], wa);
    stg256u(&g_Bh[n], wb);
}

// ---------------- K7: edge MLP output (2 edges/thread, half2 math, 50% occ) ----------------
#define EO_TB 256
__global__ void __launch_bounds__(EO_TB, 4) k_edge_out(
    const int* __restrict__ ei, const float* __restrict__ eattr,
    const float* __restrict__ we1, const float* __restrict__ we2,
    const float* __restrict__ be2, float* __restrict__ out) {
    __shared__ __half2 sWc2[5 * 8];   // we1 rows 32..36 as half2 (k-pairs)
    __shared__ __half2 sW22[8];       // we2 as half2
    __shared__ float sb2;
    int t = threadIdx.x;
    if (t < 40) {
        int r = t >> 3, kk = t & 7;
        sWc2[t] = __floats2half2_rn(we1[(32 + r) * 16 + 2 * kk],
                                    we1[(32 + r) * 16 + 2 * kk + 1]);
    }
    if (t < 8) sW22[t] = __floats2half2_rn(we2[2 * t], we2[2 * t + 1]);
    if (t == 0) sb2 = be2[0];
    __syncthreads();

    int gt = blockIdx.x * EO_TB + t;
    int base_e = gt * 2;                       // NE % (2*256) == 0
    int2 s2 = *reinterpret_cast<const int2*>(ei + base_e);
    int2 d2 = *reinterpret_cast<const int2*>(ei + NE + base_e);

    V8 pa0 = ldg256u(&g_Ah[s2.x]);
    V8 pb0 = ldg256u(&g_Bh[d2.x]);
    V8 pa1 = ldg256u(&g_Ah[s2.y]);
    V8 pb1 = ldg256u(&g_Bh[d2.y]);

    // 10 eattr floats (8B-aligned: base_e*5*4 = gt*40)
    float ea[10];
    const float2* ep = reinterpret_cast<const float2*>(eattr + (long)base_e * EF);
#pragma unroll
    for (int q = 0; q < 5; q++) {
        float2 v = ep[q];
        ea[2 * q + 0] = v.x;
        ea[2 * q + 1] = v.y;
    }

    const __half2 z2 = __float2half2_rn(0.f);
    float res[2];
#pragma unroll
    for (int j = 0; j < 2; j++) {
        const V8& PA = j ? pa1 : pa0;
        const V8& PB = j ? pb1 : pb0;
        const unsigned aw[8] = {PA.a.x, PA.a.y, PA.a.z, PA.a.w, PA.b.x, PA.b.y, PA.b.z, PA.b.w};
        const unsigned bw[8] = {PB.a.x, PB.a.y, PB.a.z, PB.a.w, PB.b.x, PB.b.y, PB.b.z, PB.b.w};
        __half2 h2[8];
#pragma unroll
        for (int i = 0; i < 8; i++) {
            h2[i] = __hadd2(*reinterpret_cast<const __half2*>(&aw[i]),
                            *reinterpret_cast<const __half2*>(&bw[i]));
        }
#pragma unroll
        for (int r = 0; r < EF; r++) {
            __half2 ev = __float2half2_rn(ea[5 * j + r]);
#pragma unroll
            for (int i = 0; i < 8; i++) h2[i] = __hfma2(ev, sWc2[r * 8 + i], h2[i]);
        }
        __half2 acc0 = z2, acc1 = z2;
#pragma unroll
        for (int i = 0; i < 4; i++) {
            acc0 = __hfma2(__hmax2(h2[i], z2),     sW22[i],     acc0);
            acc1 = __hfma2(__hmax2(h2[4 + i], z2), sW22[4 + i], acc1);
        }
        float2 f0 = __half22float2(acc0);
        float2 f1 = __half22float2(acc1);
        res[j] = sb2 + ((f0.x + f0.y) + (f1.x + f1.y));
    }
    *reinterpret_cast<float2*>(out + base_e) = make_float2(res[0], res[1]);
}

extern "C" void kernel_launch(void* const* d_in, const int* in_sizes, int n_in,
                              void* d_out, int out_size) {
    const int*   seq   = (const int*)d_in[0];
    const float* xcov  = (const float*)d_in[1];
    const int*   ei    = (const int*)d_in[2];
    const float* eattr = (const float*)d_in[3];
    const int*   batch = (const int*)d_in[4];
    const float* embed = (const float*)d_in[5];
    const float* w1    = (const float*)d_in[6];
    const float* b1    = (const float*)d_in[7];
    const float* w2    = (const float*)d_in[8];
    const float* b2    = (const float*)d_in[9];
    const float* we1   = (const float*)d_in[10];
    const float* be1   = (const float*)d_in[11];
    const float* we2   = (const float*)d_in[12];
    const float* be2   = (const float*)d_in[13];
    float* out = (float*)d_out;

    static bool attr_set = false;
    if (!attr_set) {
        cudaFuncSetAttribute((const void*)k_deg_compact,
                             cudaFuncAttributeMaxDynamicSharedMemorySize, NND);
        attr_set = true;
    }

    const int TB = 256;
    const int nb_e2 = NE / (EO_TB * 2);           // 6250
    const int nb_n = (NND + TB - 1) / TB;

    k_zero_small<<<nb_n, TB>>>(batch);
    k_deg_compact<<<DC_BLOCKS, DC_THREADS, NND>>>(ei);
    k_encode<<<nb_n, TB>>>(seq, xcov, embed, w1, b1);
    k_aggregate<0><<<128, TB>>>();
    k_finalize1<<<nb_n, TB>>>(w2, b2);
    k_aggregate<1><<<128, TB>>>();
    k_finalize2<<<nb_n, TB>>>(we1, be1);
    k_edge_out<<<nb_e2, EO_TB>>>(ei, eattr, we1, we2, be2, out);
}

// round 12
// speedup vs baseline: 1.2749x; 1.0196x over previous
#include <cuda_runtime.h>
#include <cuda_fp16.h>
#include <math.h>

#define NND 100000
#define NE  3200000
#define LTOK 64
#define HID 16
#define EF  5

struct __align__(32) V8 { uint4 a, b; };
struct __align__(32) F8 { float4 a, b; };

// ---- scratch (device globals; no allocation allowed) ----
__device__ int   g_deg[NND];
__device__ F8    g_Ms1[NND * 2];   // row n = [2n],[2n+1]; UNSCALED X@w1+b1
__device__ F8    g_Ms2[NND * 2];   // pre-scaled by dinv
__device__ F8    g_agg1[NND * 2];
__device__ F8    g_agg2[NND * 2];
__device__ V8    g_Ah[NND];        // A row = 16 half = 32B
__device__ V8    g_Bh[NND];
__device__ __align__(16) int2 g_ve[NE + 2];
__device__ __align__(16) unsigned char g_b8[NND];  // batch as uint8 (64 graphs)
__device__ int   g_vcnt;

__device__ __forceinline__ void red_add_v4(float* p, float4 v) {
    asm volatile("red.global.add.v4.f32 [%0], {%1, %2, %3, %4};"
                 :: "l"(p), "f"(v.x), "f"(v.y), "f"(v.z), "f"(v.w) : "memory");
}
__device__ __forceinline__ V8 ldg256u(const V8* p) {
    V8 r;
    asm volatile("ld.global.nc.v8.b32 {%0,%1,%2,%3,%4,%5,%6,%7}, [%8];"
        : "=r"(r.a.x), "=r"(r.a.y), "=r"(r.a.z), "=r"(r.a.w),
          "=r"(r.b.x), "=r"(r.b.y), "=r"(r.b.z), "=r"(r.b.w)
        : "l"(p));
    return r;
}
__device__ __forceinline__ F8 ldg256f(const F8* p) {
    F8 r;
    asm volatile("ld.global.nc.v8.f32 {%0,%1,%2,%3,%4,%5,%6,%7}, [%8];"
        : "=f"(r.a.x), "=f"(r.a.y), "=f"(r.a.z), "=f"(r.a.w),
          "=f"(r.b.x), "=f"(r.b.y), "=f"(r.b.z), "=f"(r.b.w)
        : "l"(p));
    return r;
}
__device__ __forceinline__ void stg256f(F8* p, const float* v) {
    asm volatile("st.global.v8.f32 [%0], {%1,%2,%3,%4,%5,%6,%7,%8};"
        :: "l"(p), "f"(v[0]), "f"(v[1]), "f"(v[2]), "f"(v[3]),
           "f"(v[4]), "f"(v[5]), "f"(v[6]), "f"(v[7]) : "memory");
}
__device__ __forceinline__ void stg256u(V8* p, const unsigned* v) {
    asm volatile("st.global.v8.b32 [%0], {%1,%2,%3,%4,%5,%6,%7,%8};"
        :: "l"(p), "r"(v[0]), "r"(v[1]), "r"(v[2]), "r"(v[3]),
           "r"(v[4]), "r"(v[5]), "r"(v[6]), "r"(v[7]) : "memory");
}
__device__ __forceinline__ float dinv_of(int deg) {
    return rsqrtf((float)deg + 1.0f + 1e-8f);
}

// ---------------- K0: zero degree + counter + pack batch->u8 ----------------
__global__ void k_zero_small(const int* __restrict__ batch) {
    int i = blockIdx.x * blockDim.x + threadIdx.x;
    if (i < NND) {
        g_deg[i] = 0;
        g_b8[i] = (unsigned char)batch[i];
    }
    if (i == 0) g_vcnt = 0;
}

// ---------------- K1: degree + valid-edge compaction via smem batch table ----------------
#define DC_BLOCKS 296
#define DC_THREADS 512
__global__ void __launch_bounds__(DC_THREADS) k_deg_compact(const int* __restrict__ ei) {
    extern __shared__ unsigned char s_b8[];   // NND bytes (100000)
    {
        const int4* src = reinterpret_cast<const int4*>(g_b8);
        int4* dst = reinterpret_cast<int4*>(s_b8);
        for (int j = threadIdx.x; j < NND / 16; j += DC_THREADS) dst[j] = src[j];
    }
    __syncthreads();

    const int NCH = NE / 8;                       // 400000 chunks of 8 edges
    const int STRIDE = DC_BLOCKS * DC_THREADS;    // 151552
    const int ITERS = (NCH + STRIDE - 1) / STRIDE; // 3
    int gtid = blockIdx.x * DC_THREADS + threadIdx.x;
    int lane = threadIdx.x & 31;

    for (int it = 0; it < ITERS; it++) {
        int i = gtid + it * STRIDE;
        bool active = (i < NCH);
        int sv[8], dv[8];
        bool v[8];
        int cnt = 0;
        if (active) {
            int base_e = i * 8;
            V8 sa = ldg256u(reinterpret_cast<const V8*>(ei + base_e));
            V8 da = ldg256u(reinterpret_cast<const V8*>(ei + NE + base_e));
            sv[0]=sa.a.x; sv[1]=sa.a.y; sv[2]=sa.a.z; sv[3]=sa.a.w;
            sv[4]=sa.b.x; sv[5]=sa.b.y; sv[6]=sa.b.z; sv[7]=sa.b.w;
            dv[0]=da.a.x; dv[1]=da.a.y; dv[2]=da.a.z; dv[3]=da.a.w;
            dv[4]=da.b.x; dv[5]=da.b.y; dv[6]=da.b.z; dv[7]=da.b.w;
#pragma unroll
            for (int j = 0; j < 8; j++) {
                v[j] = (s_b8[sv[j]] == s_b8[dv[j]]);
                if (v[j]) { atomicAdd(&g_deg[sv[j]], 1); cnt++; }
            }
        } else {
#pragma unroll
            for (int j = 0; j < 8; j++) v[j] = false;
        }
        int incl = cnt;
#pragma unroll
        for (int off = 1; off < 32; off <<= 1) {
            int nv = __shfl_up_sync(0xffffffffu, incl, off);
            if (lane >= off) incl += nv;
        }
        int total = __shfl_sync(0xffffffffu, incl, 31);
        int basew = 0;
        if (lane == 31 && total > 0) basew = atomicAdd(&g_vcnt, total);
        basew = __shfl_sync(0xffffffffu, basew, 31);
        int pos = basew + incl - cnt;
#pragma unroll
        for (int j = 0; j < 8; j++) {
            if (v[j]) g_ve[pos++] = make_int2(sv[j], dv[j]);
        }
    }
}

// ---------------- K2: encode (independent): UNSCALED M1; zero agg1+agg2 ----------------
__global__ void k_encode(const int* __restrict__ seq, const float* __restrict__ xcov,
                         const float* __restrict__ embed, const float* __restrict__ w1,
                         const float* __restrict__ b1) {
    __shared__ float s_emb[6 * 16];
    __shared__ float s_w1[17 * 16];
    __shared__ float s_b1[16];
    int t = threadIdx.x;
    for (int j = t; j < 96; j += blockDim.x) s_emb[j] = embed[j];
    for (int j = t; j < 272; j += blockDim.x) s_w1[j] = w1[j];
    if (t < 16) s_b1[t] = b1[t];
    __syncthreads();

    int n = blockIdx.x * blockDim.x + t;
    if (n >= NND) return;

    float zr[8] = {0.f,0.f,0.f,0.f,0.f,0.f,0.f,0.f};
    stg256f(&g_agg1[2 * n + 0], zr);
    stg256f(&g_agg1[2 * n + 1], zr);
    stg256f(&g_agg2[2 * n + 0], zr);
    stg256f(&g_agg2[2 * n + 1], zr);

    int c1 = 0, c2 = 0, c3 = 0, c4 = 0, c5 = 0;
    const V8* tp = reinterpret_cast<const V8*>(seq + (long)n * LTOK);
#pragma unroll
    for (int i = 0; i < 8; i++) {
        V8 v = ldg256u(tp + i);
        int tok[8] = {(int)v.a.x, (int)v.a.y, (int)v.a.z, (int)v.a.w,
                      (int)v.b.x, (int)v.b.y, (int)v.b.z, (int)v.b.w};
#pragma unroll
        for (int j = 0; j < 8; j++) {
            int tk = tok[j];
            c1 += (tk == 1); c2 += (tk == 2); c3 += (tk == 3);
            c4 += (tk == 4); c5 += (tk == 5);
        }
    }
    int nz = c1 + c2 + c3 + c4 + c5;
    float inv = 1.0f / fmaxf((float)nz, 1.0f);
    float f1 = c1 * inv, f2 = c2 * inv, f3 = c3 * inv, f4 = c4 * inv, f5 = c5 * inv;

    float x[17];
#pragma unroll
    for (int k = 0; k < 16; k++) {
        x[k] = f1 * s_emb[16 + k] + f2 * s_emb[32 + k] + f3 * s_emb[48 + k]
             + f4 * s_emb[64 + k] + f5 * s_emb[80 + k];
    }
    x[16] = xcov[n];

    float m[16];
#pragma unroll
    for (int k = 0; k < 16; k++) {
        float s = s_b1[k];
#pragma unroll
        for (int j = 0; j < 17; j++) s += x[j] * s_w1[j * 16 + k];
        m[k] = s;   // UNSCALED
    }
    stg256f(&g_Ms1[2 * n + 0], m);
    stg256f(&g_Ms1[2 * n + 1], m + 8);
}

// ---------------- K3/K5: aggregation; layer0 gathers deg[dst] and scales ----------------
template <int LAYER>
__global__ void k_aggregate() {
    int cnt = g_vcnt;
    int npair = (cnt + 1) >> 1;
    int stride = gridDim.x * blockDim.x;
    const F8* Ms = (LAYER == 0) ? g_Ms1 : g_Ms2;
    float* agg = (LAYER == 0) ? (float*)g_agg1 : (float*)g_agg2;
    for (int i = blockIdx.x * blockDim.x + threadIdx.x; i < npair; i += stride) {
        int4 e2 = *reinterpret_cast<const int4*>(&g_ve[2 * i]);
        bool second = (2 * i + 1 < cnt);
        F8 r0a = ldg256f(Ms + 2 * e2.y + 0);
        F8 r0b = ldg256f(Ms + 2 * e2.y + 1);
        F8 r1a, r1b;
        if (second) {
            r1a = ldg256f(Ms + 2 * e2.w + 0);
            r1b = ldg256f(Ms + 2 * e2.w + 1);
        }
        if (LAYER == 0) {
            float c0 = dinv_of(__ldg(&g_deg[e2.y]));
            float* f0 = reinterpret_cast<float*>(&r0a);
#pragma unroll
            for (int k = 0; k < 8; k++) f0[k] *= c0;
            float* f0b = reinterpret_cast<float*>(&r0b);
#pragma unroll
            for (int k = 0; k < 8; k++) f0b[k] *= c0;
            if (second) {
                float c1 = dinv_of(__ldg(&g_deg[e2.w]));
                float* f1 = reinterpret_cast<float*>(&r1a);
#pragma unroll
                for (int k = 0; k < 8; k++) f1[k] *= c1;
                float* f1b = reinterpret_cast<float*>(&r1b);
#pragma unroll
                for (int k = 0; k < 8; k++) f1b[k] *= c1;
            }
        }
        float* ap0 = agg + e2.x * 16;
        red_add_v4(ap0 + 0,  r0a.a);
        red_add_v4(ap0 + 4,  r0a.b);
        red_add_v4(ap0 + 8,  r0b.a);
        red_add_v4(ap0 + 12, r0b.b);
        if (second) {
            float* ap1 = agg + e2.z * 16;
            red_add_v4(ap1 + 0,  r1a.a);
            red_add_v4(ap1 + 4,  r1a.b);
            red_add_v4(ap1 + 8,  r1b.a);
            red_add_v4(ap1 + 12, r1b.b);
        }
    }
}

// ---------------- K4: H1 = relu(dinv*agg1 + dinv^2*M1); Ms2 = dinv*(H1@w2+b2) ----------------
__global__ void k_finalize1(const float* __restrict__ w2, const float* __restrict__ b2) {
    __shared__ float sW[16 * 16];
    __shared__ float sb[16];
    int t = threadIdx.x;
    for (int j = t; j < 256; j += blockDim.x) sW[j] = w2[j];
    if (t < 16) sb[t] = b2[t];
    __syncthreads();

    int n = blockIdx.x * blockDim.x + t;
    if (n >= NND) return;
    float dinv = dinv_of(g_deg[n]);
    float d2 = dinv * dinv;

    F8 aa = ldg256f(&g_agg1[2 * n + 0]);
    F8 ab = ldg256f(&g_agg1[2 * n + 1]);
    F8 ma = ldg256f(&g_Ms1[2 * n + 0]);
    F8 mb = ldg256f(&g_Ms1[2 * n + 1]);
    const float* av = reinterpret_cast<const float*>(&aa);
    const float* mv = reinterpret_cast<const float*>(&ma);
    float h[16];
#pragma unroll
    for (int k = 0; k < 8; k++) h[k] = fmaxf(dinv * av[k] + d2 * mv[k], 0.f);
    const float* av2 = reinterpret_cast<const float*>(&ab);
    const float* mv2 = reinterpret_cast<const float*>(&mb);
#pragma unroll
    for (int k = 0; k < 8; k++) h[8 + k] = fmaxf(dinv * av2[k] + d2 * mv2[k], 0.f);

    float m2[16];
#pragma unroll
    for (int k = 0; k < 16; k++) {
        float s = sb[k];
#pragma unroll
        for (int j = 0; j < 16; j++) s += h[j] * sW[j * 16 + k];
        m2[k] = s * dinv;  // pre-scale
    }
    stg256f(&g_Ms2[2 * n + 0], m2);
    stg256f(&g_Ms2[2 * n + 1], m2 + 8);
}

// ---------------- K6: H2 -> A,B stored fp16 (v8 store) ----------------
__global__ void k_finalize2(const float* __restrict__ we1, const float* __restrict__ be1) {
    __shared__ float sW[32 * 16];
    __shared__ float sb[16];
    int t = threadIdx.x;
    for (int j = t; j < 512; j += blockDim.x) sW[j] = we1[j];
    if (t < 16) sb[t] = be1[t];
    __syncthreads();

    int n = blockIdx.x * blockDim.x + t;
    if (n >= NND) return;
    float dinv = dinv_of(g_deg[n]);
    F8 aa = ldg256f(&g_agg2[2 * n + 0]);
    F8 ab = ldg256f(&g_agg2[2 * n + 1]);
    F8 ma = ldg256f(&g_Ms2[2 * n + 0]);
    F8 mb = ldg256f(&g_Ms2[2 * n + 1]);
    const float* av0 = reinterpret_cast<const float*>(&aa);
    const float* mv0 = reinterpret_cast<const float*>(&ma);
    const float* av1 = reinterpret_cast<const float*>(&ab);
    const float* mv1 = reinterpret_cast<const float*>(&mb);
    float h[16];
#pragma unroll
    for (int k = 0; k < 8; k++) h[k] = fmaxf(dinv * (av0[k] + mv0[k]), 0.f);
#pragma unroll
    for (int k = 0; k < 8; k++) h[8 + k] = fmaxf(dinv * (av1[k] + mv1[k]), 0.f);

    float av[16], bv[16];
#pragma unroll
    for (int k = 0; k < 16; k++) {
        float sa = sb[k];
        float sbv = 0.f;
#pragma unroll
        for (int j = 0; j < 16; j++) {
            sa  += h[j] * sW[j * 16 + k];
            sbv += h[j] * sW[(16 + j) * 16 + k];
        }
        av[k] = sa; bv[k] = sbv;
    }
    unsigned wa[8], wb[8];
#pragma unroll
    for (int i = 0; i < 8; i++) {
        __half2 pa = __floats2half2_rn(av[2 * i], av[2 * i + 1]);
        __half2 pb = __floats2half2_rn(bv[2 * i], bv[2 * i + 1]);
        wa[i] = *reinterpret_cast<unsigned*>(&pa);
        wb[i] = *reinterpret_cast<unsigned*>(&pb);
    }
    stg256u(&g_Ah[n], wa);
    stg256u(&g_Bh[n], wb);
}

// ---------------- K7: edge MLP output (2 edges/thread, half2 math, 50% occ) ----------------
#define EO_TB 256
__global__ void __launch_bounds__(EO_TB, 4) k_edge_out(
    const int* __restrict__ ei, const float* __restrict__ eattr,
    const float* __restrict__ we1, const float* __restrict__ we2,
    const float* __restrict__ be2, float* __restrict__ out) {
    __shared__ __half2 sWc2[5 * 8];   // we1 rows 32..36 as half2 (k-pairs)
    __shared__ __half2 sW22[8];       // we2 as half2
    __shared__ float sb2;
    int t = threadIdx.x;
    if (t < 40) {
        int r = t >> 3, kk = t & 7;
        sWc2[t] = __floats2half2_rn(we1[(32 + r) * 16 + 2 * kk],
                                    we1[(32 + r) * 16 + 2 * kk + 1]);
    }
    if (t < 8) sW22[t] = __floats2half2_rn(we2[2 * t], we2[2 * t + 1]);
    if (t == 0) sb2 = be2[0];
    __syncthreads();

    int gt = blockIdx.x * EO_TB + t;
    int base_e = gt * 2;                       // NE % (2*256) == 0
    int2 s2 = *reinterpret_cast<const int2*>(ei + base_e);
    int2 d2 = *reinterpret_cast<const int2*>(ei + NE + base_e);

    V8 pa0 = ldg256u(&g_Ah[s2.x]);
    V8 pb0 = ldg256u(&g_Bh[d2.x]);
    V8 pa1 = ldg256u(&g_Ah[s2.y]);
    V8 pb1 = ldg256u(&g_Bh[d2.y]);

    float ea[10];
    const float2* ep = reinterpret_cast<const float2*>(eattr + (long)base_e * EF);
#pragma unroll
    for (int q = 0; q < 5; q++) {
        float2 v = ep[q];
        ea[2 * q + 0] = v.x;
        ea[2 * q + 1] = v.y;
    }

    const __half2 z2 = __float2half2_rn(0.f);
    float res[2];
#pragma unroll
    for (int j = 0; j < 2; j++) {
        const V8& PA = j ? pa1 : pa0;
        const V8& PB = j ? pb1 : pb0;
        const unsigned aw[8] = {PA.a.x, PA.a.y, PA.a.z, PA.a.w, PA.b.x, PA.b.y, PA.b.z, PA.b.w};
        const unsigned bw[8] = {PB.a.x, PB.a.y, PB.a.z, PB.a.w, PB.b.x, PB.b.y, PB.b.z, PB.b.w};
        __half2 h2[8];
#pragma unroll
        for (int i = 0; i < 8; i++) {
            h2[i] = __hadd2(*reinterpret_cast<const __half2*>(&aw[i]),
                            *reinterpret_cast<const __half2*>(&bw[i]));
        }
#pragma unroll
        for (int r = 0; r < EF; r++) {
            __half2 ev = __float2half2_rn(ea[5 * j + r]);
#pragma unroll
            for (int i = 0; i < 8; i++) h2[i] = __hfma2(ev, sWc2[r * 8 + i], h2[i]);
        }
        __half2 acc0 = z2, acc1 = z2;
#pragma unroll
        for (int i = 0; i < 4; i++) {
            acc0 = __hfma2(__hmax2(h2[i], z2),     sW22[i],     acc0);
            acc1 = __hfma2(__hmax2(h2[4 + i], z2), sW22[4 + i], acc1);
        }
        float2 f0 = __half22float2(acc0);
        float2 f1 = __half22float2(acc1);
        res[j] = sb2 + ((f0.x + f0.y) + (f1.x + f1.y));
    }
    *reinterpret_cast<float2*>(out + base_e) = make_float2(res[0], res[1]);
}

extern "C" void kernel_launch(void* const* d_in, const int* in_sizes, int n_in,
                              void* d_out, int out_size) {
    const int*   seq   = (const int*)d_in[0];
    const float* xcov  = (const float*)d_in[1];
    const int*   ei    = (const int*)d_in[2];
    const float* eattr = (const float*)d_in[3];
    const int*   batch = (const int*)d_in[4];
    const float* embed = (const float*)d_in[5];
    const float* w1    = (const float*)d_in[6];
    const float* b1    = (const float*)d_in[7];
    const float* w2    = (const float*)d_in[8];
    const float* b2    = (const float*)d_in[9];
    const float* we1   = (const float*)d_in[10];
    const float* be1   = (const float*)d_in[11];
    const float* we2   = (const float*)d_in[12];
    const float* be2   = (const float*)d_in[13];
    float* out = (float*)d_out;

    static cudaStream_t s1;
    static cudaEvent_t ev_fork, ev_join;
    static bool init_done = false;
    if (!init_done) {
        cudaFuncSetAttribute((const void*)k_deg_compact,
                             cudaFuncAttributeMaxDynamicSharedMemorySize, NND);
        cudaStreamCreateWithFlags(&s1, cudaStreamNonBlocking);
        cudaEventCreateWithFlags(&ev_fork, cudaEventDisableTiming);
        cudaEventCreateWithFlags(&ev_join, cudaEventDisableTiming);
        init_done = true;
    }

    const int TB = 256;
    const int nb_e2 = NE / (EO_TB * 2);           // 6250
    const int nb_n = (NND + TB - 1) / TB;

    // fork: encode runs concurrently with zero + deg_compact
    cudaEventRecord(ev_fork, 0);
    cudaStreamWaitEvent(s1, ev_fork, 0);
    k_encode<<<nb_n, TB, 0, s1>>>(seq, xcov, embed, w1, b1);
    cudaEventRecord(ev_join, s1);

    k_zero_small<<<nb_n, TB>>>(batch);
    k_deg_compact<<<DC_BLOCKS, DC_THREADS, NND>>>(ei);

    // join
    cudaStreamWaitEvent(0, ev_join, 0);

    k_aggregate<0><<<128, TB>>>();
    k_finalize1<<<nb_n, TB>>>(w2, b2);
    k_aggregate<1><<<128, TB>>>();
    k_finalize2<<<nb_n, TB>>>(we1, be1);
    k_edge_out<<<nb_e2, EO_TB>>>(ei, eattr, we1, we2, be2, out);
}

// round 13
// speedup vs baseline: 1.3427x; 1.0532x over previous
#include <cuda_runtime.h>
#include <cuda_fp16.h>
#include <math.h>

#define NND 100000
#define NE  3200000
#define LTOK 64
#define HID 16
#define EF  5

struct __align__(32) V8 { uint4 a, b; };
struct __align__(32) F8 { float4 a, b; };

// ---- scratch (device globals; no allocation allowed) ----
__device__ int   g_deg[NND];
__device__ F8    g_Ms1[NND * 2];   // UNSCALED X@w1+b1
__device__ F8    g_Ms2[NND * 2];   // pre-scaled by dinv
__device__ F8    g_agg1[NND * 2];
__device__ F8    g_agg2[NND * 2];
__device__ V8    g_Ah[NND];
__device__ V8    g_Bh[NND];
__device__ __align__(16) int2 g_ve[NE + 2];
__device__ __align__(16) unsigned char g_b8[NND];
__device__ int   g_vcnt;

__device__ __forceinline__ void red_add_v4(float* p, float4 v) {
    asm volatile("red.global.add.v4.f32 [%0], {%1, %2, %3, %4};"
                 :: "l"(p), "f"(v.x), "f"(v.y), "f"(v.z), "f"(v.w) : "memory");
}
__device__ __forceinline__ V8 ldg256u(const V8* p) {
    V8 r;
    asm volatile("ld.global.nc.v8.b32 {%0,%1,%2,%3,%4,%5,%6,%7}, [%8];"
        : "=r"(r.a.x), "=r"(r.a.y), "=r"(r.a.z), "=r"(r.a.w),
          "=r"(r.b.x), "=r"(r.b.y), "=r"(r.b.z), "=r"(r.b.w)
        : "l"(p));
    return r;
}
__device__ __forceinline__ F8 ldg256f(const F8* p) {
    F8 r;
    asm volatile("ld.global.nc.v8.f32 {%0,%1,%2,%3,%4,%5,%6,%7}, [%8];"
        : "=f"(r.a.x), "=f"(r.a.y), "=f"(r.a.z), "=f"(r.a.w),
          "=f"(r.b.x), "=f"(r.b.y), "=f"(r.b.z), "=f"(r.b.w)
        : "l"(p));
    return r;
}
__device__ __forceinline__ void stg256f(F8* p, const float* v) {
    asm volatile("st.global.v8.f32 [%0], {%1,%2,%3,%4,%5,%6,%7,%8};"
        :: "l"(p), "f"(v[0]), "f"(v[1]), "f"(v[2]), "f"(v[3]),
           "f"(v[4]), "f"(v[5]), "f"(v[6]), "f"(v[7]) : "memory");
}
__device__ __forceinline__ void stg256u(V8* p, const unsigned* v) {
    asm volatile("st.global.v8.b32 [%0], {%1,%2,%3,%4,%5,%6,%7,%8};"
        :: "l"(p), "r"(v[0]), "r"(v[1]), "r"(v[2]), "r"(v[3]),
           "r"(v[4]), "r"(v[5]), "r"(v[6]), "r"(v[7]) : "memory");
}
__device__ __forceinline__ float dinv_of(int deg) {
    return rsqrtf((float)deg + 1.0f + 1e-8f);
}

// ---------------- K0: zero degree + counter + pack batch->u8 ----------------
__global__ void k_zero_small(const int* __restrict__ batch) {
    cudaTriggerProgrammaticLaunchCompletion();
    int i = blockIdx.x * blockDim.x + threadIdx.x;
    if (i < NND) {
        g_deg[i] = 0;
        g_b8[i] = (unsigned char)batch[i];
    }
    if (i == 0) g_vcnt = 0;
}

// ---------------- K1: degree + valid-edge compaction via smem batch table ----------------
#define DC_BLOCKS 296
#define DC_THREADS 512
__global__ void __launch_bounds__(DC_THREADS) k_deg_compact(const int* __restrict__ ei) {
    cudaTriggerProgrammaticLaunchCompletion();
    cudaGridDependencySynchronize();   // wait k_zero (b8 table, deg=0)
    extern __shared__ unsigned char s_b8[];   // NND bytes
    {
        const int4* src = reinterpret_cast<const int4*>(g_b8);
        int4* dst = reinterpret_cast<int4*>(s_b8);
        for (int j = threadIdx.x; j < NND / 16; j += DC_THREADS) dst[j] = src[j];
    }
    __syncthreads();

    const int NCH = NE / 8;
    const int STRIDE = DC_BLOCKS * DC_THREADS;
    const int ITERS = (NCH + STRIDE - 1) / STRIDE;
    int gtid = blockIdx.x * DC_THREADS + threadIdx.x;
    int lane = threadIdx.x & 31;

    for (int it = 0; it < ITERS; it++) {
        int i = gtid + it * STRIDE;
        bool active = (i < NCH);
        int sv[8], dv[8];
        bool v[8];
        int cnt = 0;
        if (active) {
            int base_e = i * 8;
            V8 sa = ldg256u(reinterpret_cast<const V8*>(ei + base_e));
            V8 da = ldg256u(reinterpret_cast<const V8*>(ei + NE + base_e));
            sv[0]=sa.a.x; sv[1]=sa.a.y; sv[2]=sa.a.z; sv[3]=sa.a.w;
            sv[4]=sa.b.x; sv[5]=sa.b.y; sv[6]=sa.b.z; sv[7]=sa.b.w;
            dv[0]=da.a.x; dv[1]=da.a.y; dv[2]=da.a.z; dv[3]=da.a.w;
            dv[4]=da.b.x; dv[5]=da.b.y; dv[6]=da.b.z; dv[7]=da.b.w;
#pragma unroll
            for (int j = 0; j < 8; j++) {
                v[j] = (s_b8[sv[j]] == s_b8[dv[j]]);
                if (v[j]) { atomicAdd(&g_deg[sv[j]], 1); cnt++; }
            }
        } else {
#pragma unroll
            for (int j = 0; j < 8; j++) v[j] = false;
        }
        int incl = cnt;
#pragma unroll
        for (int off = 1; off < 32; off <<= 1) {
            int nv = __shfl_up_sync(0xffffffffu, incl, off);
            if (lane >= off) incl += nv;
        }
        int total = __shfl_sync(0xffffffffu, incl, 31);
        int basew = 0;
        if (lane == 31 && total > 0) basew = atomicAdd(&g_vcnt, total);
        basew = __shfl_sync(0xffffffffu, basew, 31);
        int pos = basew + incl - cnt;
#pragma unroll
        for (int j = 0; j < 8; j++) {
            if (v[j]) g_ve[pos++] = make_int2(sv[j], dv[j]);
        }
    }
}

// ---------------- K2: encode (independent stream): UNSCALED M1; zero agg1+agg2 ----------------
__global__ void k_encode(const int* __restrict__ seq, const float* __restrict__ xcov,
                         const float* __restrict__ embed, const float* __restrict__ w1,
                         const float* __restrict__ b1) {
    __shared__ float s_emb[6 * 16];
    __shared__ float s_w1[17 * 16];
    __shared__ float s_b1[16];
    int t = threadIdx.x;
    for (int j = t; j < 96; j += blockDim.x) s_emb[j] = embed[j];
    for (int j = t; j < 272; j += blockDim.x) s_w1[j] = w1[j];
    if (t < 16) s_b1[t] = b1[t];
    __syncthreads();

    int n = blockIdx.x * blockDim.x + t;
    if (n >= NND) return;

    float zr[8] = {0.f,0.f,0.f,0.f,0.f,0.f,0.f,0.f};
    stg256f(&g_agg1[2 * n + 0], zr);
    stg256f(&g_agg1[2 * n + 1], zr);
    stg256f(&g_agg2[2 * n + 0], zr);
    stg256f(&g_agg2[2 * n + 1], zr);

    int c1 = 0, c2 = 0, c3 = 0, c4 = 0, c5 = 0;
    const V8* tp = reinterpret_cast<const V8*>(seq + (long)n * LTOK);
#pragma unroll
    for (int i = 0; i < 8; i++) {
        V8 v = ldg256u(tp + i);
        int tok[8] = {(int)v.a.x, (int)v.a.y, (int)v.a.z, (int)v.a.w,
                      (int)v.b.x, (int)v.b.y, (int)v.b.z, (int)v.b.w};
#pragma unroll
        for (int j = 0; j < 8; j++) {
            int tk = tok[j];
            c1 += (tk == 1); c2 += (tk == 2); c3 += (tk == 3);
            c4 += (tk == 4); c5 += (tk == 5);
        }
    }
    int nz = c1 + c2 + c3 + c4 + c5;
    float inv = 1.0f / fmaxf((float)nz, 1.0f);
    float f1 = c1 * inv, f2 = c2 * inv, f3 = c3 * inv, f4 = c4 * inv, f5 = c5 * inv;

    float x[17];
#pragma unroll
    for (int k = 0; k < 16; k++) {
        x[k] = f1 * s_emb[16 + k] + f2 * s_emb[32 + k] + f3 * s_emb[48 + k]
             + f4 * s_emb[64 + k] + f5 * s_emb[80 + k];
    }
    x[16] = xcov[n];

    float m[16];
#pragma unroll
    for (int k = 0; k < 16; k++) {
        float s = s_b1[k];
#pragma unroll
        for (int j = 0; j < 17; j++) s += x[j] * s_w1[j * 16 + k];
        m[k] = s;   // UNSCALED
    }
    stg256f(&g_Ms1[2 * n + 0], m);
    stg256f(&g_Ms1[2 * n + 1], m + 8);
}

// ---------------- K3/K5: aggregation; layer0 gathers deg[dst] and scales ----------------
template <int LAYER>
__global__ void k_aggregate() {
    cudaTriggerProgrammaticLaunchCompletion();
    cudaGridDependencySynchronize();
    int cnt = g_vcnt;
    int npair = (cnt + 1) >> 1;
    int stride = gridDim.x * blockDim.x;
    const F8* Ms = (LAYER == 0) ? g_Ms1 : g_Ms2;
    float* agg = (LAYER == 0) ? (float*)g_agg1 : (float*)g_agg2;
    for (int i = blockIdx.x * blockDim.x + threadIdx.x; i < npair; i += stride) {
        int4 e2 = *reinterpret_cast<const int4*>(&g_ve[2 * i]);
        bool second = (2 * i + 1 < cnt);
        F8 r0a = ldg256f(Ms + 2 * e2.y + 0);
        F8 r0b = ldg256f(Ms + 2 * e2.y + 1);
        F8 r1a, r1b;
        if (second) {
            r1a = ldg256f(Ms + 2 * e2.w + 0);
            r1b = ldg256f(Ms + 2 * e2.w + 1);
        }
        if (LAYER == 0) {
            float c0 = dinv_of(__ldg(&g_deg[e2.y]));
            float* f0 = reinterpret_cast<float*>(&r0a);
#pragma unroll
            for (int k = 0; k < 8; k++) f0[k] *= c0;
            float* f0b = reinterpret_cast<float*>(&r0b);
#pragma unroll
            for (int k = 0; k < 8; k++) f0b[k] *= c0;
            if (second) {
                float c1 = dinv_of(__ldg(&g_deg[e2.w]));
                float* f1 = reinterpret_cast<float*>(&r1a);
#pragma unroll
                for (int k = 0; k < 8; k++) f1[k] *= c1;
                float* f1b = reinterpret_cast<float*>(&r1b);
#pragma unroll
                for (int k = 0; k < 8; k++) f1b[k] *= c1;
            }
        }
        float* ap0 = agg + e2.x * 16;
        red_add_v4(ap0 + 0,  r0a.a);
        red_add_v4(ap0 + 4,  r0a.b);
        red_add_v4(ap0 + 8,  r0b.a);
        red_add_v4(ap0 + 12, r0b.b);
        if (second) {
            float* ap1 = agg + e2.z * 16;
            red_add_v4(ap1 + 0,  r1a.a);
            red_add_v4(ap1 + 4,  r1a.b);
            red_add_v4(ap1 + 8,  r1b.a);
            red_add_v4(ap1 + 12, r1b.b);
        }
    }
}

// ---------------- K4: H1 = relu(dinv*agg1 + dinv^2*M1); Ms2 = dinv*(H1@w2+b2) ----------------
__global__ void k_finalize1(const float* __restrict__ w2, const float* __restrict__ b2) {
    cudaTriggerProgrammaticLaunchCompletion();
    __shared__ float sW[16 * 16];
    __shared__ float sb[16];
    int t = threadIdx.x;
    for (int j = t; j < 256; j += blockDim.x) sW[j] = w2[j];
    if (t < 16) sb[t] = b2[t];
    __syncthreads();
    cudaGridDependencySynchronize();

    int n = blockIdx.x * blockDim.x + t;
    if (n >= NND) return;
    float dinv = dinv_of(g_deg[n]);
    float d2 = dinv * dinv;

    F8 aa = ldg256f(&g_agg1[2 * n + 0]);
    F8 ab = ldg256f(&g_agg1[2 * n + 1]);
    F8 ma = ldg256f(&g_Ms1[2 * n + 0]);
    F8 mb = ldg256f(&g_Ms1[2 * n + 1]);
    const float* av = reinterpret_cast<const float*>(&aa);
    const float* mv = reinterpret_cast<const float*>(&ma);
    float h[16];
#pragma unroll
    for (int k = 0; k < 8; k++) h[k] = fmaxf(dinv * av[k] + d2 * mv[k], 0.f);
    const float* av2 = reinterpret_cast<const float*>(&ab);
    const float* mv2 = reinterpret_cast<const float*>(&mb);
#pragma unroll
    for (int k = 0; k < 8; k++) h[8 + k] = fmaxf(dinv * av2[k] + d2 * mv2[k], 0.f);

    float m2[16];
#pragma unroll
    for (int k = 0; k < 16; k++) {
        float s = sb[k];
#pragma unroll
        for (int j = 0; j < 16; j++) s += h[j] * sW[j * 16 + k];
        m2[k] = s * dinv;  // pre-scale
    }
    stg256f(&g_Ms2[2 * n + 0], m2);
    stg256f(&g_Ms2[2 * n + 1], m2 + 8);
}

// ---------------- K6: H2 -> A,B stored fp16 (v8 store) ----------------
__global__ void k_finalize2(const float* __restrict__ we1, const float* __restrict__ be1) {
    cudaTriggerProgrammaticLaunchCompletion();
    __shared__ float sW[32 * 16];
    __shared__ float sb[16];
    int t = threadIdx.x;
    for (int j = t; j < 512; j += blockDim.x) sW[j] = we1[j];
    if (t < 16) sb[t] = be1[t];
    __syncthreads();
    cudaGridDependencySynchronize();

    int n = blockIdx.x * blockDim.x + t;
    if (n >= NND) return;
    float dinv = dinv_of(g_deg[n]);
    F8 aa = ldg256f(&g_agg2[2 * n + 0]);
    F8 ab = ldg256f(&g_agg2[2 * n + 1]);
    F8 ma = ldg256f(&g_Ms2[2 * n + 0]);
    F8 mb = ldg256f(&g_Ms2[2 * n + 1]);
    const float* av0 = reinterpret_cast<const float*>(&aa);
    const float* mv0 = reinterpret_cast<const float*>(&ma);
    const float* av1 = reinterpret_cast<const float*>(&ab);
    const float* mv1 = reinterpret_cast<const float*>(&mb);
    float h[16];
#pragma unroll
    for (int k = 0; k < 8; k++) h[k] = fmaxf(dinv * (av0[k] + mv0[k]), 0.f);
#pragma unroll
    for (int k = 0; k < 8; k++) h[8 + k] = fmaxf(dinv * (av1[k] + mv1[k]), 0.f);

    float av[16], bv[16];
#pragma unroll
    for (int k = 0; k < 16; k++) {
        float sa = sb[k];
        float sbv = 0.f;
#pragma unroll
        for (int j = 0; j < 16; j++) {
            sa  += h[j] * sW[j * 16 + k];
            sbv += h[j] * sW[(16 + j) * 16 + k];
        }
        av[k] = sa; bv[k] = sbv;
    }
    unsigned wa[8], wb[8];
#pragma unroll
    for (int i = 0; i < 8; i++) {
        __half2 pa = __floats2half2_rn(av[2 * i], av[2 * i + 1]);
        __half2 pb = __floats2half2_rn(bv[2 * i], bv[2 * i + 1]);
        wa[i] = *reinterpret_cast<unsigned*>(&pa);
        wb[i] = *reinterpret_cast<unsigned*>(&pb);
    }
    stg256u(&g_Ah[n], wa);
    stg256u(&g_Bh[n], wb);
}

// ---------------- K7: edge MLP output (2 edges/thread; input streaming pre-sync) ----------------
#define EO_TB 256
__global__ void __launch_bounds__(EO_TB, 4) k_edge_out(
    const int* __restrict__ ei, const float* __restrict__ eattr,
    const float* __restrict__ we1, const float* __restrict__ we2,
    const float* __restrict__ be2, float* __restrict__ out) {
    __shared__ __half2 sWc2[5 * 8];
    __shared__ __half2 sW22[8];
    __shared__ float sb2;
    int t = threadIdx.x;
    if (t < 40) {
        int r = t >> 3, kk = t & 7;
        sWc2[t] = __floats2half2_rn(we1[(32 + r) * 16 + 2 * kk],
                                    we1[(32 + r) * 16 + 2 * kk + 1]);
    }
    if (t < 8) sW22[t] = __floats2half2_rn(we2[2 * t], we2[2 * t + 1]);
    if (t == 0) sb2 = be2[0];
    __syncthreads();

    int gt = blockIdx.x * EO_TB + t;
    int base_e = gt * 2;
    // pure-input streaming (pre-sync: overlaps finalize2 tail)
    int2 s2 = *reinterpret_cast<const int2*>(ei + base_e);
    int2 d2 = *reinterpret_cast<const int2*>(ei + NE + base_e);
    float ea[10];
    const float2* ep = reinterpret_cast<const float2*>(eattr + (long)base_e * EF);
#pragma unroll
    for (int q = 0; q < 5; q++) {
        float2 v = ep[q];
        ea[2 * q + 0] = v.x;
        ea[2 * q + 1] = v.y;
    }

    cudaGridDependencySynchronize();   // wait finalize2 (A/B ready)

    V8 pa0 = ldg256u(&g_Ah[s2.x]);
    V8 pb0 = ldg256u(&g_Bh[d2.x]);
    V8 pa1 = ldg256u(&g_Ah[s2.y]);
    V8 pb1 = ldg256u(&g_Bh[d2.y]);

    const __half2 z2 = __float2half2_rn(0.f);
    float res[2];
#pragma unroll
    for (int j = 0; j < 2; j++) {
        const V8& PA = j ? pa1 : pa0;
        const V8& PB = j ? pb1 : pb0;
        const unsigned aw[8] = {PA.a.x, PA.a.y, PA.a.z, PA.a.w, PA.b.x, PA.b.y, PA.b.z, PA.b.w};
        const unsigned bw[8] = {PB.a.x, PB.a.y, PB.a.z, PB.a.w, PB.b.x, PB.b.y, PB.b.z, PB.b.w};
        __half2 h2[8];
#pragma unroll
        for (int i = 0; i < 8; i++) {
            h2[i] = __hadd2(*reinterpret_cast<const __half2*>(&aw[i]),
                            *reinterpret_cast<const __half2*>(&bw[i]));
        }
#pragma unroll
        for (int r = 0; r < EF; r++) {
            __half2 ev = __float2half2_rn(ea[5 * j + r]);
#pragma unroll
            for (int i = 0; i < 8; i++) h2[i] = __hfma2(ev, sWc2[r * 8 + i], h2[i]);
        }
        __half2 acc0 = z2, acc1 = z2;
#pragma unroll
        for (int i = 0; i < 4; i++) {
            acc0 = __hfma2(__hmax2(h2[i], z2),     sW22[i],     acc0);
            acc1 = __hfma2(__hmax2(h2[4 + i], z2), sW22[4 + i], acc1);
        }
        float2 f0 = __half22float2(acc0);
        float2 f1 = __half22float2(acc1);
        res[j] = sb2 + ((f0.x + f0.y) + (f1.x + f1.y));
    }
    *reinterpret_cast<float2*>(out + base_e) = make_float2(res[0], res[1]);
}

extern "C" void kernel_launch(void* const* d_in, const int* in_sizes, int n_in,
                              void* d_out, int out_size) {
    const int*   seq   = (const int*)d_in[0];
    const float* xcov  = (const float*)d_in[1];
    const int*   ei    = (const int*)d_in[2];
    const float* eattr = (const float*)d_in[3];
    const int*   batch = (const int*)d_in[4];
    const float* embed = (const float*)d_in[5];
    const float* w1    = (const float*)d_in[6];
    const float* b1    = (const float*)d_in[7];
    const float* w2    = (const float*)d_in[8];
    const float* b2    = (const float*)d_in[9];
    const float* we1   = (const float*)d_in[10];
    const float* be1   = (const float*)d_in[11];
    const float* we2   = (const float*)d_in[12];
    const float* be2   = (const float*)d_in[13];
    float* out = (float*)d_out;

    static cudaStream_t s1;
    static cudaEvent_t ev_fork, ev_join;
    static bool init_done = false;
    if (!init_done) {
        cudaFuncSetAttribute((const void*)k_deg_compact,
                             cudaFuncAttributeMaxDynamicSharedMemorySize, NND);
        cudaStreamCreateWithFlags(&s1, cudaStreamNonBlocking);
        cudaEventCreateWithFlags(&ev_fork, cudaEventDisableTiming);
        cudaEventCreateWithFlags(&ev_join, cudaEventDisableTiming);
        init_done = true;
    }

    const int TB = 256;
    const int nb_e2 = NE / (EO_TB * 2);           // 6250
    const int nb_n = (NND + TB - 1) / TB;

    cudaLaunchAttribute pdl;
    pdl.id = cudaLaunchAttributeProgrammaticStreamSerialization;
    pdl.val.programmaticStreamSerializationAllowed = 1;

    // fork: encode runs concurrently with zero + deg_compact
    cudaEventRecord(ev_fork, 0);
    cudaStreamWaitEvent(s1, ev_fork, 0);
    k_encode<<<nb_n, TB, 0, s1>>>(seq, xcov, embed, w1, b1);
    cudaEventRecord(ev_join, s1);

    k_zero_small<<<nb_n, TB>>>(batch);

    {
        cudaLaunchConfig_t cfg = {};
        cfg.gridDim = dim3(DC_BLOCKS); cfg.blockDim = dim3(DC_THREADS);
        cfg.dynamicSmemBytes = NND; cfg.stream = 0;
        cfg.attrs = &pdl; cfg.numAttrs = 1;
        cudaLaunchKernelEx(&cfg, k_deg_compact, ei);
    }

    // join: aggregate<0> also needs encode's Ms1
    cudaStreamWaitEvent(0, ev_join, 0);

    {
        cudaLaunchConfig_t cfg = {};
        cfg.gridDim = dim3(128); cfg.blockDim = dim3(TB); cfg.stream = 0;
        cfg.attrs = &pdl; cfg.numAttrs = 1;
        cudaLaunchKernelEx(&cfg, k_aggregate<0>);
    }
    {
        cudaLaunchConfig_t cfg = {};
        cfg.gridDim = dim3(nb_n); cfg.blockDim = dim3(TB); cfg.stream = 0;
        cfg.attrs = &pdl; cfg.numAttrs = 1;
        cudaLaunchKernelEx(&cfg, k_finalize1, w2, b2);
    }
    {
        cudaLaunchConfig_t cfg = {};
        cfg.gridDim = dim3(128); cfg.blockDim = dim3(TB); cfg.stream = 0;
        cfg.attrs = &pdl; cfg.numAttrs = 1;
        cudaLaunchKernelEx(&cfg, k_aggregate<1>);
    }
    {
        cudaLaunchConfig_t cfg = {};
        cfg.gridDim = dim3(nb_n); cfg.blockDim = dim3(TB); cfg.stream = 0;
        cfg.attrs = &pdl; cfg.numAttrs = 1;
        cudaLaunchKernelEx(&cfg, k_finalize2, we1, be1);
    }
    {
        cudaLaunchConfig_t cfg = {};
        cfg.gridDim = dim3(nb_e2); cfg.blockDim = dim3(EO_TB); cfg.stream = 0;
        cfg.attrs = &pdl; cfg.numAttrs = 1;
        cudaLaunchKernelEx(&cfg, k_edge_out, ei, eattr, we1, we2, be2, out);
    }
}

// round 14
// speedup vs baseline: 1.3432x; 1.0004x over previous
#include <cuda_runtime.h>
#include <cuda_fp16.h>
#include <math.h>

#define NND 100000
#define NE  3200000
#define LTOK 64
#define HID 16
#define EF  5

struct __align__(32) V8 { uint4 a, b; };
struct __align__(32) F8 { float4 a, b; };

// ---- scratch (device globals; no allocation allowed) ----
__device__ int   g_deg[NND];
__device__ int   g_start[NND];     // CSR bucket start per src
__device__ int   g_cur[NND];       // scatter cursor
__device__ int   g_csr[NE];        // dst list, bucketed by src
__device__ F8    g_Ms1[NND * 2];   // UNSCALED X@w1+b1
__device__ F8    g_Ms2[NND * 2];   // pre-scaled by dinv
__device__ V8    g_Ah[NND];
__device__ V8    g_Bh[NND];
__device__ __align__(16) int2 g_ve[NE + 2];
__device__ __align__(16) unsigned char g_b8[NND];
__device__ int   g_vcnt;
__device__ int   g_total;

__device__ __forceinline__ V8 ldg256u(const V8* p) {
    V8 r;
    asm volatile("ld.global.nc.v8.b32 {%0,%1,%2,%3,%4,%5,%6,%7}, [%8];"
        : "=r"(r.a.x), "=r"(r.a.y), "=r"(r.a.z), "=r"(r.a.w),
          "=r"(r.b.x), "=r"(r.b.y), "=r"(r.b.z), "=r"(r.b.w)
        : "l"(p));
    return r;
}
__device__ __forceinline__ F8 ldg256f(const F8* p) {
    F8 r;
    asm volatile("ld.global.nc.v8.f32 {%0,%1,%2,%3,%4,%5,%6,%7}, [%8];"
        : "=f"(r.a.x), "=f"(r.a.y), "=f"(r.a.z), "=f"(r.a.w),
          "=f"(r.b.x), "=f"(r.b.y), "=f"(r.b.z), "=f"(r.b.w)
        : "l"(p));
    return r;
}
__device__ __forceinline__ void stg256f(F8* p, const float* v) {
    asm volatile("st.global.v8.f32 [%0], {%1,%2,%3,%4,%5,%6,%7,%8};"
        :: "l"(p), "f"(v[0]), "f"(v[1]), "f"(v[2]), "f"(v[3]),
           "f"(v[4]), "f"(v[5]), "f"(v[6]), "f"(v[7]) : "memory");
}
__device__ __forceinline__ void stg256u(V8* p, const unsigned* v) {
    asm volatile("st.global.v8.b32 [%0], {%1,%2,%3,%4,%5,%6,%7,%8};"
        :: "l"(p), "r"(v[0]), "r"(v[1]), "r"(v[2]), "r"(v[3]),
           "r"(v[4]), "r"(v[5]), "r"(v[6]), "r"(v[7]) : "memory");
}
__device__ __forceinline__ float dinv_of(int deg) {
    return rsqrtf((float)deg + 1.0f + 1e-8f);
}

// ---------------- K0: zero counters + pack batch->u8 ----------------
__global__ void k_zero_small(const int* __restrict__ batch) {
    cudaTriggerProgrammaticLaunchCompletion();
    int i = blockIdx.x * blockDim.x + threadIdx.x;
    if (i < NND) {
        g_deg[i] = 0;
        g_b8[i] = (unsigned char)batch[i];
    }
    if (i == 0) { g_vcnt = 0; g_total = 0; }
}

// ---------------- K1: degree + valid-edge compaction via smem batch table ----------------
#define DC_BLOCKS 296
#define DC_THREADS 512
__global__ void __launch_bounds__(DC_THREADS) k_deg_compact(const int* __restrict__ ei) {
    cudaTriggerProgrammaticLaunchCompletion();
    cudaGridDependencySynchronize();
    extern __shared__ unsigned char s_b8[];
    {
        const int4* src = reinterpret_cast<const int4*>(g_b8);
        int4* dst = reinterpret_cast<int4*>(s_b8);
        for (int j = threadIdx.x; j < NND / 16; j += DC_THREADS) dst[j] = src[j];
    }
    __syncthreads();

    const int NCH = NE / 8;
    const int STRIDE = DC_BLOCKS * DC_THREADS;
    const int ITERS = (NCH + STRIDE - 1) / STRIDE;
    int gtid = blockIdx.x * DC_THREADS + threadIdx.x;
    int lane = threadIdx.x & 31;

    for (int it = 0; it < ITERS; it++) {
        int i = gtid + it * STRIDE;
        bool active = (i < NCH);
        int sv[8], dv[8];
        bool v[8];
        int cnt = 0;
        if (active) {
            int base_e = i * 8;
            V8 sa = ldg256u(reinterpret_cast<const V8*>(ei + base_e));
            V8 da = ldg256u(reinterpret_cast<const V8*>(ei + NE + base_e));
            sv[0]=sa.a.x; sv[1]=sa.a.y; sv[2]=sa.a.z; sv[3]=sa.a.w;
            sv[4]=sa.b.x; sv[5]=sa.b.y; sv[6]=sa.b.z; sv[7]=sa.b.w;
            dv[0]=da.a.x; dv[1]=da.a.y; dv[2]=da.a.z; dv[3]=da.a.w;
            dv[4]=da.b.x; dv[5]=da.b.y; dv[6]=da.b.z; dv[7]=da.b.w;
#pragma unroll
            for (int j = 0; j < 8; j++) {
                v[j] = (s_b8[sv[j]] == s_b8[dv[j]]);
                if (v[j]) { atomicAdd(&g_deg[sv[j]], 1); cnt++; }
            }
        } else {
#pragma unroll
            for (int j = 0; j < 8; j++) v[j] = false;
        }
        int incl = cnt;
#pragma unroll
        for (int off = 1; off < 32; off <<= 1) {
            int nv = __shfl_up_sync(0xffffffffu, incl, off);
            if (lane >= off) incl += nv;
        }
        int total = __shfl_sync(0xffffffffu, incl, 31);
        int basew = 0;
        if (lane == 31 && total > 0) basew = atomicAdd(&g_vcnt, total);
        basew = __shfl_sync(0xffffffffu, basew, 31);
        int pos = basew + incl - cnt;
#pragma unroll
        for (int j = 0; j < 8; j++) {
            if (v[j]) g_ve[pos++] = make_int2(sv[j], dv[j]);
        }
    }
}

// ---------------- K2: encode (independent stream): UNSCALED M1 ----------------
__global__ void k_encode(const int* __restrict__ seq, const float* __restrict__ xcov,
                         const float* __restrict__ embed, const float* __restrict__ w1,
                         const float* __restrict__ b1) {
    __shared__ float s_emb[6 * 16];
    __shared__ float s_w1[17 * 16];
    __shared__ float s_b1[16];
    int t = threadIdx.x;
    for (int j = t; j < 96; j += blockDim.x) s_emb[j] = embed[j];
    for (int j = t; j < 272; j += blockDim.x) s_w1[j] = w1[j];
    if (t < 16) s_b1[t] = b1[t];
    __syncthreads();

    int n = blockIdx.x * blockDim.x + t;
    if (n >= NND) return;

    int c1 = 0, c2 = 0, c3 = 0, c4 = 0, c5 = 0;
    const V8* tp = reinterpret_cast<const V8*>(seq + (long)n * LTOK);
#pragma unroll
    for (int i = 0; i < 8; i++) {
        V8 v = ldg256u(tp + i);
        int tok[8] = {(int)v.a.x, (int)v.a.y, (int)v.a.z, (int)v.a.w,
                      (int)v.b.x, (int)v.b.y, (int)v.b.z, (int)v.b.w};
#pragma unroll
        for (int j = 0; j < 8; j++) {
            int tk = tok[j];
            c1 += (tk == 1); c2 += (tk == 2); c3 += (tk == 3);
            c4 += (tk == 4); c5 += (tk == 5);
        }
    }
    int nz = c1 + c2 + c3 + c4 + c5;
    float inv = 1.0f / fmaxf((float)nz, 1.0f);
    float f1 = c1 * inv, f2 = c2 * inv, f3 = c3 * inv, f4 = c4 * inv, f5 = c5 * inv;

    float x[17];
#pragma unroll
    for (int k = 0; k < 16; k++) {
        x[k] = f1 * s_emb[16 + k] + f2 * s_emb[32 + k] + f3 * s_emb[48 + k]
             + f4 * s_emb[64 + k] + f5 * s_emb[80 + k];
    }
    x[16] = xcov[n];

    float m[16];
#pragma unroll
    for (int k = 0; k < 16; k++) {
        float s = s_b1[k];
#pragma unroll
        for (int j = 0; j < 17; j++) s += x[j] * s_w1[j * 16 + k];
        m[k] = s;   // UNSCALED
    }
    stg256f(&g_Ms1[2 * n + 0], m);
    stg256f(&g_Ms1[2 * n + 1], m + 8);
}

// ---------------- K3: CSR offsets (warp scan + one atomic per warp) ----------------
__global__ void k_offsets() {
    cudaTriggerProgrammaticLaunchCompletion();
    cudaGridDependencySynchronize();
    int n = blockIdx.x * blockDim.x + threadIdx.x;
    int lane = threadIdx.x & 31;
    int d = (n < NND) ? g_deg[n] : 0;
    int incl = d;
#pragma unroll
    for (int off = 1; off < 32; off <<= 1) {
        int nv = __shfl_up_sync(0xffffffffu, incl, off);
        if (lane >= off) incl += nv;
    }
    int total = __shfl_sync(0xffffffffu, incl, 31);
    int base = 0;
    if (lane == 31 && total > 0) base = atomicAdd(&g_total, total);
    base = __shfl_sync(0xffffffffu, base, 31);
    int pos = base + incl - d;
    if (n < NND) {
        g_start[n] = pos;
        g_cur[n] = pos;
    }
}

// ---------------- K4: scatter valid edges into CSR buckets ----------------
__global__ void k_scatter() {
    cudaTriggerProgrammaticLaunchCompletion();
    cudaGridDependencySynchronize();
    int cnt = g_vcnt;
    int stride = gridDim.x * blockDim.x;
    for (int i = blockIdx.x * blockDim.x + threadIdx.x; i < cnt; i += stride) {
        int2 e = g_ve[i];
        int pos = atomicAdd(&g_cur[e.x], 1);
        g_csr[pos] = e.y;
    }
}

// ---------------- K5: fused agg1+fin1: h=relu(dinv*Σ dinv_d*M1[d] + dinv^2*M1[n]); Ms2 ----------------
__global__ void k_fin1(const float* __restrict__ w2, const float* __restrict__ b2) {
    cudaTriggerProgrammaticLaunchCompletion();
    __shared__ float sW[16 * 16];
    __shared__ float sb[16];
    int t = threadIdx.x;
    for (int j = t; j < 256; j += blockDim.x) sW[j] = w2[j];
    if (t < 16) sb[t] = b2[t];
    __syncthreads();
    cudaGridDependencySynchronize();

    int n = blockIdx.x * blockDim.x + t;
    if (n >= NND) return;
    int start = g_start[n];
    int cnt = g_deg[n];

    float acc[16];
#pragma unroll
    for (int k = 0; k < 16; k++) acc[k] = 0.f;
    for (int k = 0; k < cnt; k++) {
        int d = __ldg(&g_csr[start + k]);
        float c = dinv_of(__ldg(&g_deg[d]));
        F8 ra = ldg256f(&g_Ms1[2 * d + 0]);
        F8 rb = ldg256f(&g_Ms1[2 * d + 1]);
        const float* f0 = reinterpret_cast<const float*>(&ra);
        const float* f1 = reinterpret_cast<const float*>(&rb);
#pragma unroll
        for (int i = 0; i < 8; i++) acc[i] += c * f0[i];
#pragma unroll
        for (int i = 0; i < 8; i++) acc[8 + i] += c * f1[i];
    }

    float dinv = dinv_of(cnt);
    float d2 = dinv * dinv;
    F8 ma = ldg256f(&g_Ms1[2 * n + 0]);
    F8 mb = ldg256f(&g_Ms1[2 * n + 1]);
    const float* mv0 = reinterpret_cast<const float*>(&ma);
    const float* mv1 = reinterpret_cast<const float*>(&mb);
    float h[16];
#pragma unroll
    for (int k = 0; k < 8; k++) h[k] = fmaxf(dinv * acc[k] + d2 * mv0[k], 0.f);
#pragma unroll
    for (int k = 0; k < 8; k++) h[8 + k] = fmaxf(dinv * acc[8 + k] + d2 * mv1[k], 0.f);

    float m2[16];
#pragma unroll
    for (int k = 0; k < 16; k++) {
        float s = sb[k];
#pragma unroll
        for (int j = 0; j < 16; j++) s += h[j] * sW[j * 16 + k];
        m2[k] = s * dinv;   // pre-scaled
    }
    stg256f(&g_Ms2[2 * n + 0], m2);
    stg256f(&g_Ms2[2 * n + 1], m2 + 8);
}

// ---------------- K6: fused agg2+fin2: h=relu(dinv*(Σ Ms2[d] + Ms2[n])); A,B fp16 ----------------
__global__ void k_fin2(const float* __restrict__ we1, const float* __restrict__ be1) {
    cudaTriggerProgrammaticLaunchCompletion();
    __shared__ float sW[32 * 16];
    __shared__ float sb[16];
    int t = threadIdx.x;
    for (int j = t; j < 512; j += blockDim.x) sW[j] = we1[j];
    if (t < 16) sb[t] = be1[t];
    __syncthreads();
    cudaGridDependencySynchronize();

    int n = blockIdx.x * blockDim.x + t;
    if (n >= NND) return;
    int start = g_start[n];
    int cnt = g_deg[n];

    float acc[16];
#pragma unroll
    for (int k = 0; k < 16; k++) acc[k] = 0.f;
    for (int k = 0; k < cnt; k++) {
        int d = __ldg(&g_csr[start + k]);
        F8 ra = ldg256f(&g_Ms2[2 * d + 0]);
        F8 rb = ldg256f(&g_Ms2[2 * d + 1]);
        const float* f0 = reinterpret_cast<const float*>(&ra);
        const float* f1 = reinterpret_cast<const float*>(&rb);
#pragma unroll
        for (int i = 0; i < 8; i++) acc[i] += f0[i];
#pragma unroll
        for (int i = 0; i < 8; i++) acc[8 + i] += f1[i];
    }

    float dinv = dinv_of(cnt);
    F8 ma = ldg256f(&g_Ms2[2 * n + 0]);
    F8 mb = ldg256f(&g_Ms2[2 * n + 1]);
    const float* mv0 = reinterpret_cast<const float*>(&ma);
    const float* mv1 = reinterpret_cast<const float*>(&mb);
    float h[16];
#pragma unroll
    for (int k = 0; k < 8; k++) h[k] = fmaxf(dinv * (acc[k] + mv0[k]), 0.f);
#pragma unroll
    for (int k = 0; k < 8; k++) h[8 + k] = fmaxf(dinv * (acc[8 + k] + mv1[k]), 0.f);

    float av[16], bv[16];
#pragma unroll
    for (int k = 0; k < 16; k++) {
        float sa = sb[k];
        float sbv = 0.f;
#pragma unroll
        for (int j = 0; j < 16; j++) {
            sa  += h[j] * sW[j * 16 + k];
            sbv += h[j] * sW[(16 + j) * 16 + k];
        }
        av[k] = sa; bv[k] = sbv;
    }
    unsigned wa[8], wb[8];
#pragma unroll
    for (int i = 0; i < 8; i++) {
        __half2 pa = __floats2half2_rn(av[2 * i], av[2 * i + 1]);
        __half2 pb = __floats2half2_rn(bv[2 * i], bv[2 * i + 1]);
        wa[i] = *reinterpret_cast<unsigned*>(&pa);
        wb[i] = *reinterpret_cast<unsigned*>(&pb);
    }
    stg256u(&g_Ah[n], wa);
    stg256u(&g_Bh[n], wb);
}

// ---------------- K7: edge MLP output (2 edges/thread, half2, input streaming pre-sync) ----------------
#define EO_TB 256
__global__ void __launch_bounds__(EO_TB, 4) k_edge_out(
    const int* __restrict__ ei, const float* __restrict__ eattr,
    const float* __restrict__ we1, const float* __restrict__ we2,
    const float* __restrict__ be2, float* __restrict__ out) {
    __shared__ __half2 sWc2[5 * 8];
    __shared__ __half2 sW22[8];
    __shared__ float sb2;
    int t = threadIdx.x;
    if (t < 40) {
        int r = t >> 3, kk = t & 7;
        sWc2[t] = __floats2half2_rn(we1[(32 + r) * 16 + 2 * kk],
                                    we1[(32 + r) * 16 + 2 * kk + 1]);
    }
    if (t < 8) sW22[t] = __floats2half2_rn(we2[2 * t], we2[2 * t + 1]);
    if (t == 0) sb2 = be2[0];
    __syncthreads();

    int gt = blockIdx.x * EO_TB + t;
    int base_e = gt * 2;
    int2 s2 = *reinterpret_cast<const int2*>(ei + base_e);
    int2 d2 = *reinterpret_cast<const int2*>(ei + NE + base_e);
    float ea[10];
    const float2* ep = reinterpret_cast<const float2*>(eattr + (long)base_e * EF);
#pragma unroll
    for (int q = 0; q < 5; q++) {
        float2 v = ep[q];
        ea[2 * q + 0] = v.x;
        ea[2 * q + 1] = v.y;
    }

    cudaGridDependencySynchronize();

    V8 pa0 = ldg256u(&g_Ah[s2.x]);
    V8 pb0 = ldg256u(&g_Bh[d2.x]);
    V8 pa1 = ldg256u(&g_Ah[s2.y]);
    V8 pb1 = ldg256u(&g_Bh[d2.y]);

    const __half2 z2 = __float2half2_rn(0.f);
    float res[2];
#pragma unroll
    for (int j = 0; j < 2; j++) {
        const V8& PA = j ? pa1 : pa0;
        const V8& PB = j ? pb1 : pb0;
        const unsigned aw[8] = {PA.a.x, PA.a.y, PA.a.z, PA.a.w, PA.b.x, PA.b.y, PA.b.z, PA.b.w};
        const unsigned bw[8] = {PB.a.x, PB.a.y, PB.a.z, PB.a.w, PB.b.x, PB.b.y, PB.b.z, PB.b.w};
        __half2 h2[8];
#pragma unroll
        for (int i = 0; i < 8; i++) {
            h2[i] = __hadd2(*reinterpret_cast<const __half2*>(&aw[i]),
                            *reinterpret_cast<const __half2*>(&bw[i]));
        }
#pragma unroll
        for (int r = 0; r < EF; r++) {
            __half2 ev = __float2half2_rn(ea[5 * j + r]);
#pragma unroll
            for (int i = 0; i < 8; i++) h2[i] = __hfma2(ev, sWc2[r * 8 + i], h2[i]);
        }
        __half2 acc0 = z2, acc1 = z2;
#pragma unroll
        for (int i = 0; i < 4; i++) {
            acc0 = __hfma2(__hmax2(h2[i], z2),     sW22[i],     acc0);
            acc1 = __hfma2(__hmax2(h2[4 + i], z2), sW22[4 + i], acc1);
        }
        float2 f0 = __half22float2(acc0);
        float2 f1 = __half22float2(acc1);
        res[j] = sb2 + ((f0.x + f0.y) + (f1.x + f1.y));
    }
    *reinterpret_cast<float2*>(out + base_e) = make_float2(res[0], res[1]);
}

extern "C" void kernel_launch(void* const* d_in, const int* in_sizes, int n_in,
                              void* d_out, int out_size) {
    const int*   seq   = (const int*)d_in[0];
    const float* xcov  = (const float*)d_in[1];
    const int*   ei    = (const int*)d_in[2];
    const float* eattr = (const float*)d_in[3];
    const int*   batch = (const int*)d_in[4];
    const float* embed = (const float*)d_in[5];
    const float* w1    = (const float*)d_in[6];
    const float* b1    = (const float*)d_in[7];
    const float* w2    = (const float*)d_in[8];
    const float* b2    = (const float*)d_in[9];
    const float* we1   = (const float*)d_in[10];
    const float* be1   = (const float*)d_in[11];
    const float* we2   = (const float*)d_in[12];
    const float* be2   = (const float*)d_in[13];
    float* out = (float*)d_out;

    static cudaStream_t s1;
    static cudaEvent_t ev_fork, ev_join;
    static bool init_done = false;
    if (!init_done) {
        cudaFuncSetAttribute((const void*)k_deg_compact,
                             cudaFuncAttributeMaxDynamicSharedMemorySize, NND);
        cudaStreamCreateWithFlags(&s1, cudaStreamNonBlocking);
        cudaEventCreateWithFlags(&ev_fork, cudaEventDisableTiming);
        cudaEventCreateWithFlags(&ev_join, cudaEventDisableTiming);
        init_done = true;
    }

    const int TB = 256;
    const int nb_e2 = NE / (EO_TB * 2);           // 6250
    const int nb_n = (NND + TB - 1) / TB;         // 391

    cudaLaunchAttribute pdl;
    pdl.id = cudaLaunchAttributeProgrammaticStreamSerialization;
    pdl.val.programmaticStreamSerializationAllowed = 1;

    // fork: encode runs concurrently with zero + deg_compact + offsets + scatter
    cudaEventRecord(ev_fork, 0);
    cudaStreamWaitEvent(s1, ev_fork, 0);
    k_encode<<<nb_n, TB, 0, s1>>>(seq, xcov, embed, w1, b1);
    cudaEventRecord(ev_join, s1);

    k_zero_small<<<nb_n, TB>>>(batch);

    {
        cudaLaunchConfig_t cfg = {};
        cfg.gridDim = dim3(DC_BLOCKS); cfg.blockDim = dim3(DC_THREADS);
        cfg.dynamicSmemBytes = NND; cfg.stream = 0;
        cfg.attrs = &pdl; cfg.numAttrs = 1;
        cudaLaunchKernelEx(&cfg, k_deg_compact, ei);
    }
    {
        cudaLaunchConfig_t cfg = {};
        cfg.gridDim = dim3(nb_n); cfg.blockDim = dim3(TB); cfg.stream = 0;
        cfg.attrs = &pdl; cfg.numAttrs = 1;
        cudaLaunchKernelEx(&cfg, k_offsets);
    }
    {
        cudaLaunchConfig_t cfg = {};
        cfg.gridDim = dim3(128); cfg.blockDim = dim3(TB); cfg.stream = 0;
        cfg.attrs = &pdl; cfg.numAttrs = 1;
        cudaLaunchKernelEx(&cfg, k_scatter);
    }

    // join: fin1 needs encode's Ms1
    cudaStreamWaitEvent(0, ev_join, 0);

    {
        cudaLaunchConfig_t cfg = {};
        cfg.gridDim = dim3(nb_n); cfg.blockDim = dim3(TB); cfg.stream = 0;
        cfg.attrs = &pdl; cfg.numAttrs = 1;
        cudaLaunchKernelEx(&cfg, k_fin1, w2, b2);
    }
    {
        cudaLaunchConfig_t cfg = {};
        cfg.gridDim = dim3(nb_n); cfg.blockDim = dim3(TB); cfg.stream = 0;
        cfg.attrs = &pdl; cfg.numAttrs = 1;
        cudaLaunchKernelEx(&cfg, k_fin2, we1, be1);
    }
    {
        cudaLaunchConfig_t cfg = {};
        cfg.gridDim = dim3(nb_e2); cfg.blockDim = dim3(EO_TB); cfg.stream = 0;
        cfg.attrs = &pdl; cfg.numAttrs = 1;
        cudaLaunchKernelEx(&cfg, k_edge_out, ei, eattr, we1, we2, be2, out);
    }
}